// round 11
// baseline (speedup 1.0000x reference)
#include <cuda_runtime.h>
#include <cuda_bf16.h>
#include <cuda_fp16.h>
#include <cstdint>
#include <cstddef>

#define BB 2
#define SS 2048
#define DD 1024
#define HH 16
#define HDIM 64
#define MTOT (BB*SS)   // 4096

// ---------------- device-global scratch ----------------
__device__ __half g_xh[MTOT*DD];                  // x, single f16 (A-side)
__device__ __half g_Wqh[DD*DD], g_Wql[DD*DD];     // Wq/Wk f16 hi/lo (2-pass)
__device__ __half g_Wkh[DD*DD], g_Wkl[DD*DD];
__device__ __half g_Wvh[DD*DD];                   // Wv single f16 (1-pass)
__device__ __half g_Woh[DD*DD];                   // Wo single f16 (1-pass)
__device__ __half g_Qh[MTOT*DD];                  // Q single f16, pre-scaled 0.125*log2(e)
__device__ __half g_Kh[MTOT*DD];                  // K single f16
__device__ __half g_Vh[MTOT*DD];                  // V single f16
__device__ __half g_Ch[MTOT*DD];                  // ctx single f16

// ---------------- helpers ----------------
__device__ __forceinline__ uint32_t smem_u32(const void* p) {
    uint32_t a;
    asm("{ .reg .u64 t; cvta.to.shared.u64 t, %1; cvt.u32.u64 %0, t; }" : "=r"(a) : "l"(p));
    return a;
}
#define SWZ(o)   ((uint32_t)(o) ^ ((((uint32_t)(o)) >> 3) & 0x70))
#define SWZ64(o) ((uint32_t)(o) ^ ((((uint32_t)(o)) >> 3) & 0x30))

__device__ __forceinline__ void cp16(uint32_t d, const void* s) {
    asm volatile("cp.async.cg.shared.global [%0], [%1], 16;" :: "r"(d), "l"(s));
}
#define CP_COMMIT() asm volatile("cp.async.commit_group;" ::: "memory")
#define CP_WAIT1()  asm volatile("cp.async.wait_group 1;" ::: "memory")
#define CP_WAIT0()  asm volatile("cp.async.wait_group 0;" ::: "memory")

__device__ __forceinline__ void ldsm4(uint32_t* r, uint32_t a) {
    asm volatile("ldmatrix.sync.aligned.m8n8.x4.shared.b16 {%0,%1,%2,%3}, [%4];"
        : "=r"(r[0]), "=r"(r[1]), "=r"(r[2]), "=r"(r[3]) : "r"(a));
}
__device__ __forceinline__ void ldsm4t(uint32_t* r, uint32_t a) {
    asm volatile("ldmatrix.sync.aligned.m8n8.x4.trans.shared.b16 {%0,%1,%2,%3}, [%4];"
        : "=r"(r[0]), "=r"(r[1]), "=r"(r[2]), "=r"(r[3]) : "r"(a));
}
__device__ __forceinline__ void mma16816h(float* c, const uint32_t* a, const uint32_t* b) {
    asm volatile("mma.sync.aligned.m16n8k16.row.col.f32.f16.f16.f32 "
        "{%0,%1,%2,%3}, {%4,%5,%6,%7}, {%8,%9}, {%0,%1,%2,%3};"
        : "+f"(c[0]), "+f"(c[1]), "+f"(c[2]), "+f"(c[3])
        : "r"(a[0]), "r"(a[1]), "r"(a[2]), "r"(a[3]), "r"(b[0]), "r"(b[1]));
}

__device__ __forceinline__ uint32_t ex2pack(float lo, float hi) {
    uint32_t d, r;
    asm("cvt.rn.f16x2.f32 %0, %1, %2;" : "=r"(d) : "f"(hi), "f"(lo));
    asm("ex2.approx.f16x2 %0, %1;" : "=r"(r) : "r"(d));
    return r;
}
__device__ __forceinline__ float ex2f(float x) {
    float r; asm("ex2.approx.f32 %0, %1;" : "=f"(r) : "f"(x)); return r;
}

__device__ __forceinline__ uint32_t pk_h2(float v0, float v1) {
    __half2 p; p.x = __float2half_rn(v0); p.y = __float2half_rn(v1);
    return *(uint32_t*)&p;
}
__device__ __forceinline__ void pk_split_h(uint32_t& hi, uint32_t& lo, float v0, float v1) {
    __half hx = __float2half_rn(v0), hy = __float2half_rn(v1);
    __half2 ph; ph.x = hx; ph.y = hy;
    float rx = v0 - __half2float(hx), ry = v1 - __half2float(hy);
    __half2 pl; pl.x = __float2half_rn(rx); pl.y = __float2half_rn(ry);
    hi = *(uint32_t*)&ph;
    lo = *(uint32_t*)&pl;
}

// ---------------- fused fp32 -> f16 split ----------------------------------
#define XN4 (MTOT*DD/4)          // 1048576
#define WN4 (DD*DD/4)            // 262144  (= 1<<18)

__global__ __launch_bounds__(256) void split_all(const float* __restrict__ x,
                                                 const float* __restrict__ Wq,
                                                 const float* __restrict__ Wk,
                                                 const float* __restrict__ Wv,
                                                 const float* __restrict__ Wo)
{
    int i = blockIdx.x * blockDim.x + threadIdx.x;
    if (i < XN4) {
        float4 v = ((const float4*)x)[i];
        ((uint32_t*)g_xh)[i*2+0] = pk_h2(v.x, v.y);
        ((uint32_t*)g_xh)[i*2+1] = pk_h2(v.z, v.w);
        return;
    }
    int j = i - XN4;
    int w = j >> 18;
    int off = j & (WN4 - 1);
    if (w >= 2) {   // Wv / Wo: single f16
        const float* s = (w == 2) ? Wv : Wo;
        __half* hi = (w == 2) ? g_Wvh : g_Woh;
        float4 v = ((const float4*)s)[off];
        ((uint32_t*)hi)[off*2+0] = pk_h2(v.x, v.y);
        ((uint32_t*)hi)[off*2+1] = pk_h2(v.z, v.w);
        return;
    }
    const float* s = (w == 0) ? Wq : Wk;
    __half* hi = (w == 0) ? g_Wqh : g_Wkh;
    __half* lo = (w == 0) ? g_Wql : g_Wkl;
    float4 v = ((const float4*)s)[off];
    uint32_t h0, l0, h1, l1;
    pk_split_h(h0, l0, v.x, v.y);
    pk_split_h(h1, l1, v.z, v.w);
    ((uint32_t*)hi)[off*2+0] = h0; ((uint32_t*)hi)[off*2+1] = h1;
    ((uint32_t*)lo)[off*2+0] = l0; ((uint32_t*)lo)[off*2+1] = l1;
}

// ---------------- f16 HMMA GEMM core (1- or 2-pass B) ----------------------
// CTA tile 128x128, 128 threads (2x2 warps, 64x64/warp).
// K-chunk 32 (SW64, 64B rows), 2-stage cp.async, 2 CTAs/SM.
#define SM_A  0u
#define SM_BH 8192u
#define SM_BL 16384u
#define STG   24576u
#define GEMM_SMEM (2*24576)

template<bool TP>
__device__ __forceinline__ void gemm_load(uint32_t sb, int st,
    const __half* __restrict__ A,
    const __half* __restrict__ Bh, const __half* __restrict__ Bl,
    int r0, int c0, int kt, int tid)
{
    const uint32_t base = sb + (uint32_t)st * STG;
#pragma unroll
    for (int i = 0; i < 4; ++i) {
        int idx = tid + i*128;                // 0..511
        int row = idx >> 2, c16 = idx & 3;
        uint32_t so = SWZ64(row*64 + c16*16);
        size_t ga = (size_t)(r0+row)*DD + kt + c16*8;
        size_t gb = (size_t)(c0+row)*DD + kt + c16*8;
        cp16(base + SM_A  + so, A  + ga);
        cp16(base + SM_BH + so, Bh + gb);
        if (TP) cp16(base + SM_BL + so, Bl + gb);
    }
}

template<bool TP>
__device__ __forceinline__ void hgemm_core(const __half* __restrict__ A,
                                           const __half* __restrict__ Bh,
                                           const __half* __restrict__ Bl,
                                           int r0, int c0, float acc[4][8][4])
{
    extern __shared__ char smem[];
    const uint32_t sb = smem_u32(smem);
    const int tid = threadIdx.x, lane = tid & 31, wid = tid >> 5;
    const int wr = wid >> 1, wc = wid & 1;

#pragma unroll
    for (int i = 0; i < 4; ++i)
#pragma unroll
        for (int j = 0; j < 8; ++j)
#pragma unroll
            for (int e = 0; e < 4; ++e) acc[i][j][e] = 0.f;

    const int arow  = 64*wr + (lane & 15);
    const int acol8 = (lane >> 4) * 8;
    const int brow  = 64*wc + (lane & 7) + ((lane & 16) >> 1);
    const int bk8   = lane & 8;

    gemm_load<TP>(sb, 0, A, Bh, Bl, r0, c0, 0, tid);
    CP_COMMIT();

    for (int ch = 0; ch < 32; ++ch) {
        if (ch < 31) {
            gemm_load<TP>(sb, (ch+1) & 1, A, Bh, Bl, r0, c0, (ch+1)*32, tid);
            CP_COMMIT();
            CP_WAIT1();
        } else {
            CP_WAIT0();
        }
        __syncthreads();

        const uint32_t cb = sb + (uint32_t)(ch & 1) * STG;
#pragma unroll
        for (int t = 0; t < 2; ++t) {
            uint32_t fa[4][4], fbh[4][4], fbl[4][4];
#pragma unroll
            for (int mt = 0; mt < 4; ++mt) {
                uint32_t ao = SWZ64((arow + 16*mt)*64 + (t*16 + acol8)*2);
                ldsm4(fa[mt], cb + SM_A + ao);
            }
#pragma unroll
            for (int p = 0; p < 4; ++p) {
                uint32_t bo = SWZ64((brow + 16*p)*64 + (t*16 + bk8)*2);
                ldsm4(fbh[p], cb + SM_BH + bo);
                if (TP) ldsm4(fbl[p], cb + SM_BL + bo);
            }
#pragma unroll
            for (int mt = 0; mt < 4; ++mt)
#pragma unroll
                for (int p = 0; p < 4; ++p) {
                    mma16816h(acc[mt][2*p],   fa[mt], &fbh[p][0]);
                    mma16816h(acc[mt][2*p+1], fa[mt], &fbh[p][2]);
                }
            if (TP) {
#pragma unroll
                for (int mt = 0; mt < 4; ++mt)
#pragma unroll
                    for (int p = 0; p < 4; ++p) {
                        mma16816h(acc[mt][2*p],   fa[mt], &fbl[p][0]);
                        mma16816h(acc[mt][2*p+1], fa[mt], &fbl[p][2]);
                    }
            }
        }
        __syncthreads();
    }
}

__global__ __launch_bounds__(128, 2) void qkv_hmma()
{
    float acc[4][8][4];
    const int r0 = blockIdx.y * 128, c0 = blockIdx.x * 128;

    if (blockIdx.z == 0)      hgemm_core<true >(g_xh, g_Wqh, g_Wql, r0, c0, acc);
    else if (blockIdx.z == 1) hgemm_core<true >(g_xh, g_Wkh, g_Wkl, r0, c0, acc);
    else                      hgemm_core<false>(g_xh, g_Wvh, nullptr, r0, c0, acc);

    const int tid = threadIdx.x, lane = tid & 31, wid = tid >> 5;
    const int wr = wid >> 1, wc = wid & 1;
    __half* O = (blockIdx.z == 0) ? g_Qh : (blockIdx.z == 1) ? g_Kh : g_Vh;
    const float scale = (blockIdx.z == 0) ? 0.18033688f : 1.f;  // 0.125*log2(e) for Q
#pragma unroll
    for (int mt = 0; mt < 4; ++mt)
#pragma unroll
        for (int nt = 0; nt < 8; ++nt) {
            int rg = r0 + 64*wr + 16*mt + (lane >> 2);
            int cg = c0 + 64*wc + 8*nt + 2*(lane & 3);
            int bidx = rg >> 11, s = rg & 2047, h = cg >> 6, hd = cg & 63;
            size_t base = (((size_t)bidx*HH + h)*SS + s)*HDIM + hd;
            *(uint32_t*)(O + base)          = pk_h2(acc[mt][nt][0]*scale, acc[mt][nt][1]*scale);
            *(uint32_t*)(O + base + 8*HDIM) = pk_h2(acc[mt][nt][2]*scale, acc[mt][nt][3]*scale);
        }
}

__global__ __launch_bounds__(128, 2) void out_hmma(float* __restrict__ out,
                                                   const float* __restrict__ bo)
{
    float acc[4][8][4];
    const int r0 = blockIdx.y * 128, c0 = blockIdx.x * 128;
    hgemm_core<false>(g_Ch, g_Woh, nullptr, r0, c0, acc);

    const int tid = threadIdx.x, lane = tid & 31, wid = tid >> 5;
    const int wr = wid >> 1, wc = wid & 1;
#pragma unroll
    for (int mt = 0; mt < 4; ++mt)
#pragma unroll
        for (int nt = 0; nt < 8; ++nt) {
            int rg = r0 + 64*wr + 16*mt + (lane >> 2);
            int cg = c0 + 64*wc + 8*nt + 2*(lane & 3);
            float b0v = bo[cg], b1v = bo[cg+1];
            float2 o0 = make_float2(acc[mt][nt][0] + b0v, acc[mt][nt][1] + b1v);
            float2 o1 = make_float2(acc[mt][nt][2] + b0v, acc[mt][nt][3] + b1v);
            *(float2*)&out[(size_t)rg * DD + cg] = o0;
            *(float2*)&out[(size_t)(rg+8) * DD + cg] = o1;
        }
}

// ---------------- f16 causal flash attention (single-pass K & V) -----------
#define AQ   0u
#define AKV  16384u
#define KSTG 16384u
#define AKH  0u
#define AVH  8192u
#define ATTN_SMEM (16384 + 2*16384)

__device__ __forceinline__ void attn_load_kv(uint32_t sb, int st, size_t hb, int j0, int tid)
{
    const uint32_t base = sb + AKV + (uint32_t)st * KSTG;
#pragma unroll
    for (int i = 0; i < 4; ++i) {
        int idx = tid + i*128;               // 0..511
        int row = idx >> 3, c16 = idx & 7;
        uint32_t so = SWZ(row*128 + c16*16);
        size_t g = (hb + j0 + row)*HDIM + c16*8;
        cp16(base + AKH + so, g_Kh + g);
        cp16(base + AVH + so, g_Vh + g);
    }
}

__global__ __launch_bounds__(128, 2) void attn_hmma()
{
    extern __shared__ char smem[];
    const uint32_t sb = smem_u32(smem);
    const int tid = threadIdx.x, lane = tid & 31, wid = tid >> 5;
    const int qb = gridDim.x - 1 - blockIdx.x;   // heavy CTAs first
    const int h = blockIdx.y, b = blockIdx.z;
    const int q0 = qb * 128;
    const size_t hb = ((size_t)b*HH + h) * SS;

#pragma unroll
    for (int i = 0; i < 8; ++i) {
        int idx = tid + i*128;               // 0..1023
        int row = idx >> 3, c16 = idx & 7;
        uint32_t so = SWZ(row*128 + c16*16);
        cp16(sb + AQ + so, g_Qh + (hb + q0 + row)*HDIM + c16*8);
    }
    attn_load_kv(sb, 0, hb, 0, tid);
    CP_COMMIT();

    uint32_t fq[2][4][4];
    float oacc[2][8][4];
#pragma unroll
    for (int mt = 0; mt < 2; ++mt)
#pragma unroll
        for (int nt = 0; nt < 8; ++nt)
#pragma unroll
            for (int e = 0; e < 4; ++e) oacc[mt][nt][e] = 0.f;
    float m[2][2] = {{-1e30f,-1e30f},{-1e30f,-1e30f}};
    float l[2][2] = {{0.f,0.f},{0.f,0.f}};

    const int rb0 = q0 + 32*wid + (lane >> 2);
    const int ntiles = 2*qb + 2;

    for (int kt = 0; kt < ntiles; ++kt) {
        const int j0 = kt * 64;
        if (kt + 1 < ntiles) {
            attn_load_kv(sb, (kt+1) & 1, hb, j0 + 64, tid);
            CP_COMMIT();
            CP_WAIT1();
        } else {
            CP_WAIT0();
        }
        __syncthreads();

        if (kt == 0) {
#pragma unroll
            for (int mt = 0; mt < 2; ++mt)
#pragma unroll
                for (int t = 0; t < 4; ++t) {
                    uint32_t ao = SWZ((32*wid + 16*mt + (lane & 15))*128 + (t*16 + (lane >> 4)*8)*2);
                    ldsm4(fq[mt][t], sb + AQ + ao);
                }
        }

        const uint32_t kb = sb + AKV + (uint32_t)(kt & 1) * KSTG;

        // S = Q K^T   (single-pass f16)
        float sacc[2][8][4];
#pragma unroll
        for (int mt = 0; mt < 2; ++mt)
#pragma unroll
            for (int nt = 0; nt < 8; ++nt)
#pragma unroll
                for (int e = 0; e < 4; ++e) sacc[mt][nt][e] = 0.f;

#pragma unroll
        for (int t = 0; t < 4; ++t) {
#pragma unroll
            for (int p = 0; p < 4; ++p) {
                uint32_t bo_ = SWZ((16*p + (lane & 7) + ((lane & 16) >> 1))*128 + (t*16 + (lane & 8))*2);
                uint32_t kbh[4];
                ldsm4(kbh, kb + AKH + bo_);
#pragma unroll
                for (int mt = 0; mt < 2; ++mt) {
                    mma16816h(sacc[mt][2*p],   fq[mt][t], &kbh[0]);
                    mma16816h(sacc[mt][2*p+1], fq[mt][t], &kbh[2]);
                }
            }
        }

        // causal mask, online softmax (exp2), P -> packed f16 fragments
        uint32_t pp[2][8][2];
#pragma unroll
        for (int mt = 0; mt < 2; ++mt) {
            const int rbase = rb0 + 16*mt;
            if (j0 + 63 > rbase) {
#pragma unroll
                for (int nt = 0; nt < 8; ++nt) {
                    int cg = j0 + 8*nt + 2*(lane & 3);
                    if (cg   > rbase)     sacc[mt][nt][0] = -1e30f;
                    if (cg+1 > rbase)     sacc[mt][nt][1] = -1e30f;
                    if (cg   > rbase + 8) sacc[mt][nt][2] = -1e30f;
                    if (cg+1 > rbase + 8) sacc[mt][nt][3] = -1e30f;
                }
            }
            float mx0 = -1e30f, mx1 = -1e30f;
#pragma unroll
            for (int nt = 0; nt < 8; ++nt) {
                mx0 = fmaxf(mx0, fmaxf(sacc[mt][nt][0], sacc[mt][nt][1]));
                mx1 = fmaxf(mx1, fmaxf(sacc[mt][nt][2], sacc[mt][nt][3]));
            }
            mx0 = fmaxf(mx0, __shfl_xor_sync(0xffffffffu, mx0, 1));
            mx0 = fmaxf(mx0, __shfl_xor_sync(0xffffffffu, mx0, 2));
            mx1 = fmaxf(mx1, __shfl_xor_sync(0xffffffffu, mx1, 1));
            mx1 = fmaxf(mx1, __shfl_xor_sync(0xffffffffu, mx1, 2));
            const float mn0 = fmaxf(m[mt][0], mx0), mn1 = fmaxf(m[mt][1], mx1);
            const float c0f = ex2f(m[mt][0] - mn0), c1f = ex2f(m[mt][1] - mn1);
            float s0 = 0.f, s1 = 0.f;
#pragma unroll
            for (int nt = 0; nt < 8; ++nt) {
                uint32_t p01 = ex2pack(sacc[mt][nt][0] - mn0, sacc[mt][nt][1] - mn0);
                uint32_t p23 = ex2pack(sacc[mt][nt][2] - mn1, sacc[mt][nt][3] - mn1);
                pp[mt][nt][0] = p01;
                pp[mt][nt][1] = p23;
                __half2 h01 = *(__half2*)&p01;
                __half2 h23 = *(__half2*)&p23;
                s0 += __half2float(h01.x) + __half2float(h01.y);
                s1 += __half2float(h23.x) + __half2float(h23.y);
            }
            s0 += __shfl_xor_sync(0xffffffffu, s0, 1);
            s0 += __shfl_xor_sync(0xffffffffu, s0, 2);
            s1 += __shfl_xor_sync(0xffffffffu, s1, 1);
            s1 += __shfl_xor_sync(0xffffffffu, s1, 2);
            l[mt][0] = l[mt][0] * c0f + s0;
            l[mt][1] = l[mt][1] * c1f + s1;
            m[mt][0] = mn0; m[mt][1] = mn1;
#pragma unroll
            for (int nt = 0; nt < 8; ++nt) {
                oacc[mt][nt][0] *= c0f; oacc[mt][nt][1] *= c0f;
                oacc[mt][nt][2] *= c1f; oacc[mt][nt][3] *= c1f;
            }
        }

        // O += P V   (single-pass f16)
#pragma unroll
        for (int kc = 0; kc < 4; ++kc) {
#pragma unroll
            for (int p = 0; p < 4; ++p) {
                uint32_t vo = SWZ((kc*16 + (lane & 15))*128 + (16*p + ((lane >> 1) & 8))*2);
                uint32_t vbh[4];
                ldsm4t(vbh, kb + AVH + vo);
#pragma unroll
                for (int mt = 0; mt < 2; ++mt) {
                    uint32_t pa[4] = { pp[mt][2*kc][0], pp[mt][2*kc][1],
                                       pp[mt][2*kc+1][0], pp[mt][2*kc+1][1] };
                    mma16816h(oacc[mt][2*p],   pa, &vbh[0]);
                    mma16816h(oacc[mt][2*p+1], pa, &vbh[2]);
                }
            }
        }
        __syncthreads();
    }

    // epilogue: ctx as single f16 [token][d]
#pragma unroll
    for (int mt = 0; mt < 2; ++mt) {
        const float inv0 = 1.f / l[mt][0], inv1 = 1.f / l[mt][1];
        const size_t tok = ((size_t)b*SS + rb0 + 16*mt)*DD + h*HDIM;
#pragma unroll
        for (int nt = 0; nt < 8; ++nt) {
            int col = 8*nt + 2*(lane & 3);
            *(uint32_t*)(g_Ch + tok + col)        = pk_h2(oacc[mt][nt][0]*inv0, oacc[mt][nt][1]*inv0);
            *(uint32_t*)(g_Ch + tok + 8*DD + col) = pk_h2(oacc[mt][nt][2]*inv1, oacc[mt][nt][3]*inv1);
        }
    }
}

// ---------------- launch ----------------
extern "C" void kernel_launch(void* const* d_in, const int* in_sizes, int n_in,
                              void* d_out, int out_size)
{
    const float* x  = (const float*)d_in[0];
    const float* Wq = (const float*)d_in[1];
    const float* Wk = (const float*)d_in[2];
    const float* Wv = (const float*)d_in[3];
    const float* Wo = (const float*)d_in[4];
    const float* bo = (const float*)d_in[5];
    float* out = (float*)d_out;
    (void)in_sizes; (void)n_in; (void)out_size;

    static bool attr_done = false;
    if (!attr_done) {
        cudaFuncSetAttribute(qkv_hmma, cudaFuncAttributeMaxDynamicSharedMemorySize, GEMM_SMEM);
        cudaFuncSetAttribute(out_hmma, cudaFuncAttributeMaxDynamicSharedMemorySize, GEMM_SMEM);
        cudaFuncSetAttribute(attn_hmma, cudaFuncAttributeMaxDynamicSharedMemorySize, ATTN_SMEM);
        attr_done = true;
    }

    split_all<<<(XN4 + 4*WN4) / 256, 256>>>(x, Wq, Wk, Wv, Wo);

    dim3 qkv_grid(DD/128, MTOT/128, 3);
    qkv_hmma<<<qkv_grid, 128, GEMM_SMEM>>>();

    dim3 attn_grid(SS/128, HH, BB);
    attn_hmma<<<attn_grid, 128, ATTN_SMEM>>>();

    dim3 out_grid(DD/128, MTOT/128, 1);
    out_hmma<<<out_grid, 128, GEMM_SMEM>>>(out, bo);
}

// round 12
// speedup vs baseline: 1.4131x; 1.4131x over previous
#include <cuda_runtime.h>
#include <cuda_bf16.h>
#include <cuda_fp16.h>
#include <cstdint>
#include <cstddef>

#define BB 2
#define SS 2048
#define DD 1024
#define HH 16
#define HDIM 64
#define MTOT (BB*SS)   // 4096

// ---------------- device-global scratch ----------------
__device__ __half g_xh[MTOT*DD];                  // x, single f16 (A-side)
__device__ __half g_Wqh[DD*DD], g_Wql[DD*DD];     // Wq/Wk f16 hi/lo (2-pass)
__device__ __half g_Wkh[DD*DD], g_Wkl[DD*DD];
__device__ __half g_Wvh[DD*DD];                   // Wv single f16 (1-pass)
__device__ __half g_Woh[DD*DD];                   // Wo single f16 (1-pass)
__device__ __half g_Qh[MTOT*DD];                  // Q single f16, pre-scaled 0.125*log2(e)
__device__ __half g_Kh[MTOT*DD];                  // K single f16
__device__ __half g_Vh[MTOT*DD];                  // V single f16
__device__ __half g_Ch[MTOT*DD];                  // ctx single f16

// ---------------- helpers ----------------
__device__ __forceinline__ uint32_t smem_u32(const void* p) {
    uint32_t a;
    asm("{ .reg .u64 t; cvta.to.shared.u64 t, %1; cvt.u32.u64 %0, t; }" : "=r"(a) : "l"(p));
    return a;
}
#define SWZ(o)   ((uint32_t)(o) ^ ((((uint32_t)(o)) >> 3) & 0x70))
#define SWZ64(o) ((uint32_t)(o) ^ ((((uint32_t)(o)) >> 3) & 0x30))

__device__ __forceinline__ void cp16(uint32_t d, const void* s) {
    asm volatile("cp.async.cg.shared.global [%0], [%1], 16;" :: "r"(d), "l"(s));
}
#define CP_COMMIT() asm volatile("cp.async.commit_group;" ::: "memory")
#define CP_WAIT1()  asm volatile("cp.async.wait_group 1;" ::: "memory")
#define CP_WAIT0()  asm volatile("cp.async.wait_group 0;" ::: "memory")

__device__ __forceinline__ void ldsm4(uint32_t* r, uint32_t a) {
    asm volatile("ldmatrix.sync.aligned.m8n8.x4.shared.b16 {%0,%1,%2,%3}, [%4];"
        : "=r"(r[0]), "=r"(r[1]), "=r"(r[2]), "=r"(r[3]) : "r"(a));
}
__device__ __forceinline__ void ldsm4t(uint32_t* r, uint32_t a) {
    asm volatile("ldmatrix.sync.aligned.m8n8.x4.trans.shared.b16 {%0,%1,%2,%3}, [%4];"
        : "=r"(r[0]), "=r"(r[1]), "=r"(r[2]), "=r"(r[3]) : "r"(a));
}
__device__ __forceinline__ void mma16816h(float* c, const uint32_t* a, const uint32_t* b) {
    asm volatile("mma.sync.aligned.m16n8k16.row.col.f32.f16.f16.f32 "
        "{%0,%1,%2,%3}, {%4,%5,%6,%7}, {%8,%9}, {%0,%1,%2,%3};"
        : "+f"(c[0]), "+f"(c[1]), "+f"(c[2]), "+f"(c[3])
        : "r"(a[0]), "r"(a[1]), "r"(a[2]), "r"(a[3]), "r"(b[0]), "r"(b[1]));
}

__device__ __forceinline__ uint32_t ex2pack(float lo, float hi) {
    uint32_t d, r;
    asm("cvt.rn.f16x2.f32 %0, %1, %2;" : "=r"(d) : "f"(hi), "f"(lo));
    asm("ex2.approx.f16x2 %0, %1;" : "=r"(r) : "r"(d));
    return r;
}
__device__ __forceinline__ float ex2f(float x) {
    float r; asm("ex2.approx.f32 %0, %1;" : "=f"(r) : "f"(x)); return r;
}

__device__ __forceinline__ uint32_t pk_h2(float v0, float v1) {
    __half2 p; p.x = __float2half_rn(v0); p.y = __float2half_rn(v1);
    return *(uint32_t*)&p;
}
__device__ __forceinline__ void pk_split_h(uint32_t& hi, uint32_t& lo, float v0, float v1) {
    __half hx = __float2half_rn(v0), hy = __float2half_rn(v1);
    __half2 ph; ph.x = hx; ph.y = hy;
    float rx = v0 - __half2float(hx), ry = v1 - __half2float(hy);
    __half2 pl; pl.x = __float2half_rn(rx); pl.y = __float2half_rn(ry);
    hi = *(uint32_t*)&ph;
    lo = *(uint32_t*)&pl;
}

// ---------------- fused fp32 -> f16 split ----------------------------------
#define XN4 (MTOT*DD/4)          // 1048576
#define WN4 (DD*DD/4)            // 262144  (= 1<<18)

__global__ __launch_bounds__(256) void split_all(const float* __restrict__ x,
                                                 const float* __restrict__ Wq,
                                                 const float* __restrict__ Wk,
                                                 const float* __restrict__ Wv,
                                                 const float* __restrict__ Wo)
{
    int i = blockIdx.x * blockDim.x + threadIdx.x;
    if (i < XN4) {
        float4 v = ((const float4*)x)[i];
        ((uint32_t*)g_xh)[i*2+0] = pk_h2(v.x, v.y);
        ((uint32_t*)g_xh)[i*2+1] = pk_h2(v.z, v.w);
        return;
    }
    int j = i - XN4;
    int w = j >> 18;
    int off = j & (WN4 - 1);
    if (w >= 2) {   // Wv / Wo: single f16
        const float* s = (w == 2) ? Wv : Wo;
        __half* hi = (w == 2) ? g_Wvh : g_Woh;
        float4 v = ((const float4*)s)[off];
        ((uint32_t*)hi)[off*2+0] = pk_h2(v.x, v.y);
        ((uint32_t*)hi)[off*2+1] = pk_h2(v.z, v.w);
        return;
    }
    const float* s = (w == 0) ? Wq : Wk;
    __half* hi = (w == 0) ? g_Wqh : g_Wkh;
    __half* lo = (w == 0) ? g_Wql : g_Wkl;
    float4 v = ((const float4*)s)[off];
    uint32_t h0, l0, h1, l1;
    pk_split_h(h0, l0, v.x, v.y);
    pk_split_h(h1, l1, v.z, v.w);
    ((uint32_t*)hi)[off*2+0] = h0; ((uint32_t*)hi)[off*2+1] = h1;
    ((uint32_t*)lo)[off*2+0] = l0; ((uint32_t*)lo)[off*2+1] = l1;
}

// ---------------- f16 HMMA GEMM core (1- or 2-pass B, compile-time) --------
// CTA tile 128x128, 128 threads (2x2 warps, 64x64/warp).
// K-chunk 32 (SW64, 64B rows), 2-stage cp.async, 2 CTAs/SM.
#define SM_A  0u
#define SM_BH 8192u
#define SM_BL 16384u
#define STG   24576u
#define GEMM_SMEM (2*24576)

template<bool TP>
__device__ __forceinline__ void gemm_load(uint32_t sb, int st,
    const __half* __restrict__ A,
    const __half* __restrict__ Bh, const __half* __restrict__ Bl,
    int r0, int c0, int kt, int tid)
{
    const uint32_t base = sb + (uint32_t)st * STG;
#pragma unroll
    for (int i = 0; i < 4; ++i) {
        int idx = tid + i*128;                // 0..511
        int row = idx >> 2, c16 = idx & 3;
        uint32_t so = SWZ64(row*64 + c16*16);
        size_t ga = (size_t)(r0+row)*DD + kt + c16*8;
        size_t gb = (size_t)(c0+row)*DD + kt + c16*8;
        cp16(base + SM_A  + so, A  + ga);
        cp16(base + SM_BH + so, Bh + gb);
        if (TP) cp16(base + SM_BL + so, Bl + gb);
    }
}

template<bool TP>
__device__ __forceinline__ void hgemm_core(const __half* __restrict__ A,
                                           const __half* __restrict__ Bh,
                                           const __half* __restrict__ Bl,
                                           int r0, int c0, float acc[4][8][4])
{
    extern __shared__ char smem[];
    const uint32_t sb = smem_u32(smem);
    const int tid = threadIdx.x, lane = tid & 31, wid = tid >> 5;
    const int wr = wid >> 1, wc = wid & 1;

#pragma unroll
    for (int i = 0; i < 4; ++i)
#pragma unroll
        for (int j = 0; j < 8; ++j)
#pragma unroll
            for (int e = 0; e < 4; ++e) acc[i][j][e] = 0.f;

    const int arow  = 64*wr + (lane & 15);
    const int acol8 = (lane >> 4) * 8;
    const int brow  = 64*wc + (lane & 7) + ((lane & 16) >> 1);
    const int bk8   = lane & 8;

    gemm_load<TP>(sb, 0, A, Bh, Bl, r0, c0, 0, tid);
    CP_COMMIT();

    for (int ch = 0; ch < 32; ++ch) {
        if (ch < 31) {
            gemm_load<TP>(sb, (ch+1) & 1, A, Bh, Bl, r0, c0, (ch+1)*32, tid);
            CP_COMMIT();
            CP_WAIT1();
        } else {
            CP_WAIT0();
        }
        __syncthreads();

        const uint32_t cb = sb + (uint32_t)(ch & 1) * STG;
#pragma unroll
        for (int t = 0; t < 2; ++t) {
            uint32_t fa[4][4], fbh[4][4], fbl[4][4];
#pragma unroll
            for (int mt = 0; mt < 4; ++mt) {
                uint32_t ao = SWZ64((arow + 16*mt)*64 + (t*16 + acol8)*2);
                ldsm4(fa[mt], cb + SM_A + ao);
            }
#pragma unroll
            for (int p = 0; p < 4; ++p) {
                uint32_t bo = SWZ64((brow + 16*p)*64 + (t*16 + bk8)*2);
                ldsm4(fbh[p], cb + SM_BH + bo);
                if (TP) ldsm4(fbl[p], cb + SM_BL + bo);
            }
#pragma unroll
            for (int mt = 0; mt < 4; ++mt)
#pragma unroll
                for (int p = 0; p < 4; ++p) {
                    mma16816h(acc[mt][2*p],   fa[mt], &fbh[p][0]);
                    mma16816h(acc[mt][2*p+1], fa[mt], &fbh[p][2]);
                }
            if (TP) {
#pragma unroll
                for (int mt = 0; mt < 4; ++mt)
#pragma unroll
                    for (int p = 0; p < 4; ++p) {
                        mma16816h(acc[mt][2*p],   fa[mt], &fbl[p][0]);
                        mma16816h(acc[mt][2*p+1], fa[mt], &fbl[p][2]);
                    }
            }
        }
        __syncthreads();
    }
}

// epilogue writer for QKV-style head-layout f16 output
__device__ __forceinline__ void qkv_epilogue(float acc[4][8][4], __half* O,
                                             int r0, int c0, float scale)
{
    const int tid = threadIdx.x, lane = tid & 31, wid = tid >> 5;
    const int wr = wid >> 1, wc = wid & 1;
#pragma unroll
    for (int mt = 0; mt < 4; ++mt)
#pragma unroll
        for (int nt = 0; nt < 8; ++nt) {
            int rg = r0 + 64*wr + 16*mt + (lane >> 2);
            int cg = c0 + 64*wc + 8*nt + 2*(lane & 3);
            int bidx = rg >> 11, s = rg & 2047, h = cg >> 6, hd = cg & 63;
            size_t base = (((size_t)bidx*HH + h)*SS + s)*HDIM + hd;
            *(uint32_t*)(O + base)          = pk_h2(acc[mt][nt][0]*scale, acc[mt][nt][1]*scale);
            *(uint32_t*)(O + base + 8*HDIM) = pk_h2(acc[mt][nt][2]*scale, acc[mt][nt][3]*scale);
        }
}

// Q/K projections: 2-pass split weights (only <true> instantiated here)
__global__ __launch_bounds__(128, 2) void qk_hmma()
{
    float acc[4][8][4];
    const int r0 = blockIdx.y * 128, c0 = blockIdx.x * 128;
    const bool isQ = (blockIdx.z == 0);
    hgemm_core<true>(g_xh, isQ ? g_Wqh : g_Wkh, isQ ? g_Wql : g_Wkl, r0, c0, acc);
    qkv_epilogue(acc, isQ ? g_Qh : g_Kh, r0, c0, isQ ? 0.18033688f : 1.f);
}

// V projection: single-pass (only <false> instantiated here)
__global__ __launch_bounds__(128, 2) void v_hmma()
{
    float acc[4][8][4];
    const int r0 = blockIdx.y * 128, c0 = blockIdx.x * 128;
    hgemm_core<false>(g_xh, g_Wvh, nullptr, r0, c0, acc);
    qkv_epilogue(acc, g_Vh, r0, c0, 1.f);
}

__global__ __launch_bounds__(128, 2) void out_hmma(float* __restrict__ out,
                                                   const float* __restrict__ bo)
{
    float acc[4][8][4];
    const int r0 = blockIdx.y * 128, c0 = blockIdx.x * 128;
    hgemm_core<false>(g_Ch, g_Woh, nullptr, r0, c0, acc);

    const int tid = threadIdx.x, lane = tid & 31, wid = tid >> 5;
    const int wr = wid >> 1, wc = wid & 1;
#pragma unroll
    for (int mt = 0; mt < 4; ++mt)
#pragma unroll
        for (int nt = 0; nt < 8; ++nt) {
            int rg = r0 + 64*wr + 16*mt + (lane >> 2);
            int cg = c0 + 64*wc + 8*nt + 2*(lane & 3);
            float b0v = bo[cg], b1v = bo[cg+1];
            float2 o0 = make_float2(acc[mt][nt][0] + b0v, acc[mt][nt][1] + b1v);
            float2 o1 = make_float2(acc[mt][nt][2] + b0v, acc[mt][nt][3] + b1v);
            *(float2*)&out[(size_t)rg * DD + cg] = o0;
            *(float2*)&out[(size_t)(rg+8) * DD + cg] = o1;
        }
}

// ---------------- f16 causal flash attention (single-pass K & V) -----------
#define AQ   0u
#define AKV  16384u
#define KSTG 16384u
#define AKH  0u
#define AVH  8192u
#define ATTN_SMEM (16384 + 2*16384)

__device__ __forceinline__ void attn_load_kv(uint32_t sb, int st, size_t hb, int j0, int tid)
{
    const uint32_t base = sb + AKV + (uint32_t)st * KSTG;
#pragma unroll
    for (int i = 0; i < 4; ++i) {
        int idx = tid + i*128;               // 0..511
        int row = idx >> 3, c16 = idx & 7;
        uint32_t so = SWZ(row*128 + c16*16);
        size_t g = (hb + j0 + row)*HDIM + c16*8;
        cp16(base + AKH + so, g_Kh + g);
        cp16(base + AVH + so, g_Vh + g);
    }
}

__global__ __launch_bounds__(128, 2) void attn_hmma()
{
    extern __shared__ char smem[];
    const uint32_t sb = smem_u32(smem);
    const int tid = threadIdx.x, lane = tid & 31, wid = tid >> 5;
    const int qb = gridDim.x - 1 - blockIdx.x;   // heavy CTAs first
    const int h = blockIdx.y, b = blockIdx.z;
    const int q0 = qb * 128;
    const size_t hb = ((size_t)b*HH + h) * SS;

#pragma unroll
    for (int i = 0; i < 8; ++i) {
        int idx = tid + i*128;               // 0..1023
        int row = idx >> 3, c16 = idx & 7;
        uint32_t so = SWZ(row*128 + c16*16);
        cp16(sb + AQ + so, g_Qh + (hb + q0 + row)*HDIM + c16*8);
    }
    attn_load_kv(sb, 0, hb, 0, tid);
    CP_COMMIT();

    uint32_t fq[2][4][4];
    float oacc[2][8][4];
#pragma unroll
    for (int mt = 0; mt < 2; ++mt)
#pragma unroll
        for (int nt = 0; nt < 8; ++nt)
#pragma unroll
            for (int e = 0; e < 4; ++e) oacc[mt][nt][e] = 0.f;
    float m[2][2] = {{-1e30f,-1e30f},{-1e30f,-1e30f}};
    float l[2][2] = {{0.f,0.f},{0.f,0.f}};

    const int rb0 = q0 + 32*wid + (lane >> 2);
    const int ntiles = 2*qb + 2;

    for (int kt = 0; kt < ntiles; ++kt) {
        const int j0 = kt * 64;
        if (kt + 1 < ntiles) {
            attn_load_kv(sb, (kt+1) & 1, hb, j0 + 64, tid);
            CP_COMMIT();
            CP_WAIT1();
        } else {
            CP_WAIT0();
        }
        __syncthreads();

        if (kt == 0) {
#pragma unroll
            for (int mt = 0; mt < 2; ++mt)
#pragma unroll
                for (int t = 0; t < 4; ++t) {
                    uint32_t ao = SWZ((32*wid + 16*mt + (lane & 15))*128 + (t*16 + (lane >> 4)*8)*2);
                    ldsm4(fq[mt][t], sb + AQ + ao);
                }
        }

        const uint32_t kb = sb + AKV + (uint32_t)(kt & 1) * KSTG;

        // S = Q K^T   (single-pass f16)
        float sacc[2][8][4];
#pragma unroll
        for (int mt = 0; mt < 2; ++mt)
#pragma unroll
            for (int nt = 0; nt < 8; ++nt)
#pragma unroll
                for (int e = 0; e < 4; ++e) sacc[mt][nt][e] = 0.f;

#pragma unroll
        for (int t = 0; t < 4; ++t) {
#pragma unroll
            for (int p = 0; p < 4; ++p) {
                uint32_t bo_ = SWZ((16*p + (lane & 7) + ((lane & 16) >> 1))*128 + (t*16 + (lane & 8))*2);
                uint32_t kbh[4];
                ldsm4(kbh, kb + AKH + bo_);
#pragma unroll
                for (int mt = 0; mt < 2; ++mt) {
                    mma16816h(sacc[mt][2*p],   fq[mt][t], &kbh[0]);
                    mma16816h(sacc[mt][2*p+1], fq[mt][t], &kbh[2]);
                }
            }
        }

        // causal mask, online softmax (exp2), P -> packed f16 fragments
        uint32_t pp[2][8][2];
#pragma unroll
        for (int mt = 0; mt < 2; ++mt) {
            const int rbase = rb0 + 16*mt;
            if (j0 + 63 > rbase) {
#pragma unroll
                for (int nt = 0; nt < 8; ++nt) {
                    int cg = j0 + 8*nt + 2*(lane & 3);
                    if (cg   > rbase)     sacc[mt][nt][0] = -1e30f;
                    if (cg+1 > rbase)     sacc[mt][nt][1] = -1e30f;
                    if (cg   > rbase + 8) sacc[mt][nt][2] = -1e30f;
                    if (cg+1 > rbase + 8) sacc[mt][nt][3] = -1e30f;
                }
            }
            float mx0 = -1e30f, mx1 = -1e30f;
#pragma unroll
            for (int nt = 0; nt < 8; ++nt) {
                mx0 = fmaxf(mx0, fmaxf(sacc[mt][nt][0], sacc[mt][nt][1]));
                mx1 = fmaxf(mx1, fmaxf(sacc[mt][nt][2], sacc[mt][nt][3]));
            }
            mx0 = fmaxf(mx0, __shfl_xor_sync(0xffffffffu, mx0, 1));
            mx0 = fmaxf(mx0, __shfl_xor_sync(0xffffffffu, mx0, 2));
            mx1 = fmaxf(mx1, __shfl_xor_sync(0xffffffffu, mx1, 1));
            mx1 = fmaxf(mx1, __shfl_xor_sync(0xffffffffu, mx1, 2));
            const float mn0 = fmaxf(m[mt][0], mx0), mn1 = fmaxf(m[mt][1], mx1);
            const float c0f = ex2f(m[mt][0] - mn0), c1f = ex2f(m[mt][1] - mn1);
            float s0 = 0.f, s1 = 0.f;
#pragma unroll
            for (int nt = 0; nt < 8; ++nt) {
                uint32_t p01 = ex2pack(sacc[mt][nt][0] - mn0, sacc[mt][nt][1] - mn0);
                uint32_t p23 = ex2pack(sacc[mt][nt][2] - mn1, sacc[mt][nt][3] - mn1);
                pp[mt][nt][0] = p01;
                pp[mt][nt][1] = p23;
                __half2 h01 = *(__half2*)&p01;
                __half2 h23 = *(__half2*)&p23;
                s0 += __half2float(h01.x) + __half2float(h01.y);
                s1 += __half2float(h23.x) + __half2float(h23.y);
            }
            s0 += __shfl_xor_sync(0xffffffffu, s0, 1);
            s0 += __shfl_xor_sync(0xffffffffu, s0, 2);
            s1 += __shfl_xor_sync(0xffffffffu, s1, 1);
            s1 += __shfl_xor_sync(0xffffffffu, s1, 2);
            l[mt][0] = l[mt][0] * c0f + s0;
            l[mt][1] = l[mt][1] * c1f + s1;
            m[mt][0] = mn0; m[mt][1] = mn1;
#pragma unroll
            for (int nt = 0; nt < 8; ++nt) {
                oacc[mt][nt][0] *= c0f; oacc[mt][nt][1] *= c0f;
                oacc[mt][nt][2] *= c1f; oacc[mt][nt][3] *= c1f;
            }
        }

        // O += P V   (single-pass f16)
#pragma unroll
        for (int kc = 0; kc < 4; ++kc) {
#pragma unroll
            for (int p = 0; p < 4; ++p) {
                uint32_t vo = SWZ((kc*16 + (lane & 15))*128 + (16*p + ((lane >> 1) & 8))*2);
                uint32_t vbh[4];
                ldsm4t(vbh, kb + AVH + vo);
#pragma unroll
                for (int mt = 0; mt < 2; ++mt) {
                    uint32_t pa[4] = { pp[mt][2*kc][0], pp[mt][2*kc][1],
                                       pp[mt][2*kc+1][0], pp[mt][2*kc+1][1] };
                    mma16816h(oacc[mt][2*p],   pa, &vbh[0]);
                    mma16816h(oacc[mt][2*p+1], pa, &vbh[2]);
                }
            }
        }
        __syncthreads();
    }

    // epilogue: ctx as single f16 [token][d]
#pragma unroll
    for (int mt = 0; mt < 2; ++mt) {
        const float inv0 = 1.f / l[mt][0], inv1 = 1.f / l[mt][1];
        const size_t tok = ((size_t)b*SS + rb0 + 16*mt)*DD + h*HDIM;
#pragma unroll
        for (int nt = 0; nt < 8; ++nt) {
            int col = 8*nt + 2*(lane & 3);
            *(uint32_t*)(g_Ch + tok + col)        = pk_h2(oacc[mt][nt][0]*inv0, oacc[mt][nt][1]*inv0);
            *(uint32_t*)(g_Ch + tok + 8*DD + col) = pk_h2(oacc[mt][nt][2]*inv1, oacc[mt][nt][3]*inv1);
        }
    }
}

// ---------------- launch ----------------
extern "C" void kernel_launch(void* const* d_in, const int* in_sizes, int n_in,
                              void* d_out, int out_size)
{
    const float* x  = (const float*)d_in[0];
    const float* Wq = (const float*)d_in[1];
    const float* Wk = (const float*)d_in[2];
    const float* Wv = (const float*)d_in[3];
    const float* Wo = (const float*)d_in[4];
    const float* bo = (const float*)d_in[5];
    float* out = (float*)d_out;
    (void)in_sizes; (void)n_in; (void)out_size;

    static bool attr_done = false;
    if (!attr_done) {
        cudaFuncSetAttribute(qk_hmma,  cudaFuncAttributeMaxDynamicSharedMemorySize, GEMM_SMEM);
        cudaFuncSetAttribute(v_hmma,   cudaFuncAttributeMaxDynamicSharedMemorySize, GEMM_SMEM);
        cudaFuncSetAttribute(out_hmma, cudaFuncAttributeMaxDynamicSharedMemorySize, GEMM_SMEM);
        cudaFuncSetAttribute(attn_hmma, cudaFuncAttributeMaxDynamicSharedMemorySize, ATTN_SMEM);
        attr_done = true;
    }

    split_all<<<(XN4 + 4*WN4) / 256, 256>>>(x, Wq, Wk, Wv, Wo);

    dim3 qk_grid(DD/128, MTOT/128, 2);
    qk_hmma<<<qk_grid, 128, GEMM_SMEM>>>();

    dim3 v_grid(DD/128, MTOT/128, 1);
    v_hmma<<<v_grid, 128, GEMM_SMEM>>>();

    dim3 attn_grid(SS/128, HH, BB);
    attn_hmma<<<attn_grid, 128, ATTN_SMEM>>>();

    dim3 out_grid(DD/128, MTOT/128, 1);
    out_hmma<<<out_grid, 128, GEMM_SMEM>>>(out, bo);
}

// round 14
// speedup vs baseline: 1.4335x; 1.0144x over previous
#include <cuda_runtime.h>
#include <cuda_bf16.h>
#include <cuda_fp16.h>
#include <cstdint>
#include <cstddef>

#define BB 2
#define SS 2048
#define DD 1024
#define HH 16
#define HDIM 64
#define MTOT (BB*SS)   // 4096

// ---------------- device-global scratch ----------------
__device__ __half g_xh[MTOT*DD];                  // x, single f16 (A-side)
__device__ __half g_Wqh[DD*DD], g_Wql[DD*DD];     // Wq/Wk f16 hi/lo (2-pass)
__device__ __half g_Wkh[DD*DD], g_Wkl[DD*DD];
__device__ __half g_Wvh[DD*DD];                   // Wv single f16 (1-pass)
__device__ __half g_Woh[DD*DD];                   // Wo single f16 (1-pass)
__device__ __half g_Qh[MTOT*DD];                  // Q single f16, pre-scaled 0.125*log2(e)
__device__ __half g_Kh[MTOT*DD];                  // K single f16
__device__ __half g_Vh[MTOT*DD];                  // V single f16
__device__ __half g_Ch[MTOT*DD];                  // ctx single f16

// ---------------- helpers ----------------
__device__ __forceinline__ uint32_t smem_u32(const void* p) {
    uint32_t a;
    asm("{ .reg .u64 t; cvta.to.shared.u64 t, %1; cvt.u32.u64 %0, t; }" : "=r"(a) : "l"(p));
    return a;
}
#define SWZ(o)   ((uint32_t)(o) ^ ((((uint32_t)(o)) >> 3) & 0x70))
#define SWZ64(o) ((uint32_t)(o) ^ ((((uint32_t)(o)) >> 3) & 0x30))

__device__ __forceinline__ void cp16(uint32_t d, const void* s) {
    asm volatile("cp.async.cg.shared.global [%0], [%1], 16;" :: "r"(d), "l"(s));
}
#define CP_COMMIT() asm volatile("cp.async.commit_group;" ::: "memory")
#define CP_WAIT1()  asm volatile("cp.async.wait_group 1;" ::: "memory")
#define CP_WAIT0()  asm volatile("cp.async.wait_group 0;" ::: "memory")

__device__ __forceinline__ void ldsm4(uint32_t* r, uint32_t a) {
    asm volatile("ldmatrix.sync.aligned.m8n8.x4.shared.b16 {%0,%1,%2,%3}, [%4];"
        : "=r"(r[0]), "=r"(r[1]), "=r"(r[2]), "=r"(r[3]) : "r"(a));
}
__device__ __forceinline__ void ldsm4t(uint32_t* r, uint32_t a) {
    asm volatile("ldmatrix.sync.aligned.m8n8.x4.trans.shared.b16 {%0,%1,%2,%3}, [%4];"
        : "=r"(r[0]), "=r"(r[1]), "=r"(r[2]), "=r"(r[3]) : "r"(a));
}
__device__ __forceinline__ void mma16816h(float* c, const uint32_t* a, const uint32_t* b) {
    asm volatile("mma.sync.aligned.m16n8k16.row.col.f32.f16.f16.f32 "
        "{%0,%1,%2,%3}, {%4,%5,%6,%7}, {%8,%9}, {%0,%1,%2,%3};"
        : "+f"(c[0]), "+f"(c[1]), "+f"(c[2]), "+f"(c[3])
        : "r"(a[0]), "r"(a[1]), "r"(a[2]), "r"(a[3]), "r"(b[0]), "r"(b[1]));
}

__device__ __forceinline__ uint32_t ex2pack(float lo, float hi) {
    uint32_t d, r;
    asm("cvt.rn.f16x2.f32 %0, %1, %2;" : "=r"(d) : "f"(hi), "f"(lo));
    asm("ex2.approx.f16x2 %0, %1;" : "=r"(r) : "r"(d));
    return r;
}
__device__ __forceinline__ float ex2f(float x) {
    float r; asm("ex2.approx.f32 %0, %1;" : "=f"(r) : "f"(x)); return r;
}

__device__ __forceinline__ uint32_t pk_h2(float v0, float v1) {
    __half2 p; p.x = __float2half_rn(v0); p.y = __float2half_rn(v1);
    return *(uint32_t*)&p;
}
__device__ __forceinline__ void pk_split_h(uint32_t& hi, uint32_t& lo, float v0, float v1) {
    __half hx = __float2half_rn(v0), hy = __float2half_rn(v1);
    __half2 ph; ph.x = hx; ph.y = hy;
    float rx = v0 - __half2float(hx), ry = v1 - __half2float(hy);
    __half2 pl; pl.x = __float2half_rn(rx); pl.y = __float2half_rn(ry);
    hi = *(uint32_t*)&ph;
    lo = *(uint32_t*)&pl;
}

// ---------------- fused fp32 -> f16 split ----------------------------------
#define XN4 (MTOT*DD/4)          // 1048576
#define WN4 (DD*DD/4)            // 262144  (= 1<<18)

__global__ __launch_bounds__(256) void split_all(const float* __restrict__ x,
                                                 const float* __restrict__ Wq,
                                                 const float* __restrict__ Wk,
                                                 const float* __restrict__ Wv,
                                                 const float* __restrict__ Wo)
{
    int i = blockIdx.x * blockDim.x + threadIdx.x;
    if (i < XN4) {
        float4 v = ((const float4*)x)[i];
        ((uint32_t*)g_xh)[i*2+0] = pk_h2(v.x, v.y);
        ((uint32_t*)g_xh)[i*2+1] = pk_h2(v.z, v.w);
        return;
    }
    int j = i - XN4;
    int w = j >> 18;
    int off = j & (WN4 - 1);
    if (w >= 2) {   // Wv / Wo: single f16
        const float* s = (w == 2) ? Wv : Wo;
        __half* hi = (w == 2) ? g_Wvh : g_Woh;
        float4 v = ((const float4*)s)[off];
        ((uint32_t*)hi)[off*2+0] = pk_h2(v.x, v.y);
        ((uint32_t*)hi)[off*2+1] = pk_h2(v.z, v.w);
        return;
    }
    const float* s = (w == 0) ? Wq : Wk;
    __half* hi = (w == 0) ? g_Wqh : g_Wkh;
    __half* lo = (w == 0) ? g_Wql : g_Wkl;
    float4 v = ((const float4*)s)[off];
    uint32_t h0, l0, h1, l1;
    pk_split_h(h0, l0, v.x, v.y);
    pk_split_h(h1, l1, v.z, v.w);
    ((uint32_t*)hi)[off*2+0] = h0; ((uint32_t*)hi)[off*2+1] = h1;
    ((uint32_t*)lo)[off*2+0] = l0; ((uint32_t*)lo)[off*2+1] = l1;
}

// ---------------- f16 HMMA GEMM core (1- or 2-pass B, compile-time) --------
#define SM_A  0u
#define SM_BH 8192u
#define SM_BL 16384u
#define STG   24576u
#define GEMM_SMEM (2*24576)

template<bool TP>
__device__ __forceinline__ void gemm_load(uint32_t sb, int st,
    const __half* __restrict__ A,
    const __half* __restrict__ Bh, const __half* __restrict__ Bl,
    int r0, int c0, int kt, int tid)
{
    const uint32_t base = sb + (uint32_t)st * STG;
#pragma unroll
    for (int i = 0; i < 4; ++i) {
        int idx = tid + i*128;                // 0..511
        int row = idx >> 2, c16 = idx & 3;
        uint32_t so = SWZ64(row*64 + c16*16);
        size_t ga = (size_t)(r0+row)*DD + kt + c16*8;
        size_t gb = (size_t)(c0+row)*DD + kt + c16*8;
        cp16(base + SM_A  + so, A  + ga);
        cp16(base + SM_BH + so, Bh + gb);
        if (TP) cp16(base + SM_BL + so, Bl + gb);
    }
}

template<bool TP>
__device__ __forceinline__ void hgemm_core(const __half* __restrict__ A,
                                           const __half* __restrict__ Bh,
                                           const __half* __restrict__ Bl,
                                           int r0, int c0, float acc[4][8][4])
{
    extern __shared__ char smem[];
    const uint32_t sb = smem_u32(smem);
    const int tid = threadIdx.x, lane = tid & 31, wid = tid >> 5;
    const int wr = wid >> 1, wc = wid & 1;

#pragma unroll
    for (int i = 0; i < 4; ++i)
#pragma unroll
        for (int j = 0; j < 8; ++j)
#pragma unroll
            for (int e = 0; e < 4; ++e) acc[i][j][e] = 0.f;

    const int arow  = 64*wr + (lane & 15);
    const int acol8 = (lane >> 4) * 8;
    const int brow  = 64*wc + (lane & 7) + ((lane & 16) >> 1);
    const int bk8   = lane & 8;

    gemm_load<TP>(sb, 0, A, Bh, Bl, r0, c0, 0, tid);
    CP_COMMIT();

    for (int ch = 0; ch < 32; ++ch) {
        if (ch < 31) {
            gemm_load<TP>(sb, (ch+1) & 1, A, Bh, Bl, r0, c0, (ch+1)*32, tid);
            CP_COMMIT();
            CP_WAIT1();
        } else {
            CP_WAIT0();
        }
        __syncthreads();

        const uint32_t cb = sb + (uint32_t)(ch & 1) * STG;
#pragma unroll
        for (int t = 0; t < 2; ++t) {
            uint32_t fa[4][4], fbh[4][4], fbl[4][4];
#pragma unroll
            for (int mt = 0; mt < 4; ++mt) {
                uint32_t ao = SWZ64((arow + 16*mt)*64 + (t*16 + acol8)*2);
                ldsm4(fa[mt], cb + SM_A + ao);
            }
#pragma unroll
            for (int p = 0; p < 4; ++p) {
                uint32_t bo = SWZ64((brow + 16*p)*64 + (t*16 + bk8)*2);
                ldsm4(fbh[p], cb + SM_BH + bo);
                if (TP) ldsm4(fbl[p], cb + SM_BL + bo);
            }
#pragma unroll
            for (int mt = 0; mt < 4; ++mt)
#pragma unroll
                for (int p = 0; p < 4; ++p) {
                    mma16816h(acc[mt][2*p],   fa[mt], &fbh[p][0]);
                    mma16816h(acc[mt][2*p+1], fa[mt], &fbh[p][2]);
                }
            if (TP) {
#pragma unroll
                for (int mt = 0; mt < 4; ++mt)
#pragma unroll
                    for (int p = 0; p < 4; ++p) {
                        mma16816h(acc[mt][2*p],   fa[mt], &fbl[p][0]);
                        mma16816h(acc[mt][2*p+1], fa[mt], &fbl[p][2]);
                    }
            }
        }
        __syncthreads();
    }
}

// epilogue writer for QKV-style head-layout f16 output
__device__ __forceinline__ void qkv_epilogue(float acc[4][8][4], __half* O,
                                             int r0, int c0, float scale)
{
    const int tid = threadIdx.x, lane = tid & 31, wid = tid >> 5;
    const int wr = wid >> 1, wc = wid & 1;
#pragma unroll
    for (int mt = 0; mt < 4; ++mt)
#pragma unroll
        for (int nt = 0; nt < 8; ++nt) {
            int rg = r0 + 64*wr + 16*mt + (lane >> 2);
            int cg = c0 + 64*wc + 8*nt + 2*(lane & 3);
            int bidx = rg >> 11, s = rg & 2047, h = cg >> 6, hd = cg & 63;
            size_t base = (((size_t)bidx*HH + h)*SS + s)*HDIM + hd;
            *(uint32_t*)(O + base)          = pk_h2(acc[mt][nt][0]*scale, acc[mt][nt][1]*scale);
            *(uint32_t*)(O + base + 8*HDIM) = pk_h2(acc[mt][nt][2]*scale, acc[mt][nt][3]*scale);
        }
}

// Q/K projections: 2-pass split weights
__global__ __launch_bounds__(128, 2) void qk_hmma()
{
    float acc[4][8][4];
    const int r0 = blockIdx.y * 128, c0 = blockIdx.x * 128;
    const bool isQ = (blockIdx.z == 0);
    hgemm_core<true>(g_xh, isQ ? g_Wqh : g_Wkh, isQ ? g_Wql : g_Wkl, r0, c0, acc);
    qkv_epilogue(acc, isQ ? g_Qh : g_Kh, r0, c0, isQ ? 0.18033688f : 1.f);
}

// V projection: single-pass
__global__ __launch_bounds__(128, 2) void v_hmma()
{
    float acc[4][8][4];
    const int r0 = blockIdx.y * 128, c0 = blockIdx.x * 128;
    hgemm_core<false>(g_xh, g_Wvh, nullptr, r0, c0, acc);
    qkv_epilogue(acc, g_Vh, r0, c0, 1.f);
}

__global__ __launch_bounds__(128, 2) void out_hmma(float* __restrict__ out,
                                                   const float* __restrict__ bo)
{
    float acc[4][8][4];
    const int r0 = blockIdx.y * 128, c0 = blockIdx.x * 128;
    hgemm_core<false>(g_Ch, g_Woh, nullptr, r0, c0, acc);

    const int tid = threadIdx.x, lane = tid & 31, wid = tid >> 5;
    const int wr = wid >> 1, wc = wid & 1;
#pragma unroll
    for (int mt = 0; mt < 4; ++mt)
#pragma unroll
        for (int nt = 0; nt < 8; ++nt) {
            int rg = r0 + 64*wr + 16*mt + (lane >> 2);
            int cg = c0 + 64*wc + 8*nt + 2*(lane & 3);
            float b0v = bo[cg], b1v = bo[cg+1];
            float2 o0 = make_float2(acc[mt][nt][0] + b0v, acc[mt][nt][1] + b1v);
            float2 o1 = make_float2(acc[mt][nt][2] + b0v, acc[mt][nt][3] + b1v);
            *(float2*)&out[(size_t)rg * DD + cg] = o0;
            *(float2*)&out[(size_t)(rg+8) * DD + cg] = o1;
        }
}

// ---------------- f16 causal flash attention (online softmax, ones-MMA l) --
// Q/K/V single f16; online max (centers exp2 args near 0 — REQUIRED, see R12);
// row-sum l computed by an extra MMA against a ones B-fragment (no scalar sums,
// no quad shuffles for l).
#define AQ   0u
#define AKV  16384u
#define KSTG 16384u
#define AKH  0u
#define AVH  8192u
#define ATTN_SMEM (16384 + 2*16384)

__device__ __forceinline__ void attn_load_kv(uint32_t sb, int st, size_t hb, int j0, int tid)
{
    const uint32_t base = sb + AKV + (uint32_t)st * KSTG;
#pragma unroll
    for (int i = 0; i < 4; ++i) {
        int idx = tid + i*128;               // 0..511
        int row = idx >> 3, c16 = idx & 7;
        uint32_t so = SWZ(row*128 + c16*16);
        size_t g = (hb + j0 + row)*HDIM + c16*8;
        cp16(base + AKH + so, g_Kh + g);
        cp16(base + AVH + so, g_Vh + g);
    }
}

__global__ __launch_bounds__(128, 2) void attn_hmma()
{
    extern __shared__ char smem[];
    const uint32_t sb = smem_u32(smem);
    const int tid = threadIdx.x, lane = tid & 31, wid = tid >> 5;
    const int qb = gridDim.x - 1 - blockIdx.x;   // heavy CTAs first
    const int h = blockIdx.y, b = blockIdx.z;
    const int q0 = qb * 128;
    const size_t hb = ((size_t)b*HH + h) * SS;

#pragma unroll
    for (int i = 0; i < 8; ++i) {
        int idx = tid + i*128;               // 0..1023
        int row = idx >> 3, c16 = idx & 7;
        uint32_t so = SWZ(row*128 + c16*16);
        cp16(sb + AQ + so, g_Qh + (hb + q0 + row)*HDIM + c16*8);
    }
    attn_load_kv(sb, 0, hb, 0, tid);
    CP_COMMIT();

    const uint32_t ones2 = 0x3C003C00u;      // __half2(1,1)
    const uint32_t ones_frag[2] = { ones2, ones2 };

    uint32_t fq[2][4][4];
    float oacc[2][8][4];
    float lacc[2][4];                         // l via ones-MMA (cols duplicated)
#pragma unroll
    for (int mt = 0; mt < 2; ++mt) {
#pragma unroll
        for (int nt = 0; nt < 8; ++nt)
#pragma unroll
            for (int e = 0; e < 4; ++e) oacc[mt][nt][e] = 0.f;
#pragma unroll
        for (int e = 0; e < 4; ++e) lacc[mt][e] = 0.f;
    }
    float m[2][2] = {{-1e30f,-1e30f},{-1e30f,-1e30f}};

    const int rb0 = q0 + 32*wid + (lane >> 2);
    const int ntiles = 2*qb + 2;

    for (int kt = 0; kt < ntiles; ++kt) {
        const int j0 = kt * 64;
        if (kt + 1 < ntiles) {
            attn_load_kv(sb, (kt+1) & 1, hb, j0 + 64, tid);
            CP_COMMIT();
            CP_WAIT1();
        } else {
            CP_WAIT0();
        }
        __syncthreads();

        if (kt == 0) {
#pragma unroll
            for (int mt = 0; mt < 2; ++mt)
#pragma unroll
                for (int t = 0; t < 4; ++t) {
                    uint32_t ao = SWZ((32*wid + 16*mt + (lane & 15))*128 + (t*16 + (lane >> 4)*8)*2);
                    ldsm4(fq[mt][t], sb + AQ + ao);
                }
        }

        const uint32_t kb = sb + AKV + (uint32_t)(kt & 1) * KSTG;

        // S = Q K^T   (single-pass f16)
        float sacc[2][8][4];
#pragma unroll
        for (int mt = 0; mt < 2; ++mt)
#pragma unroll
            for (int nt = 0; nt < 8; ++nt)
#pragma unroll
                for (int e = 0; e < 4; ++e) sacc[mt][nt][e] = 0.f;

#pragma unroll
        for (int t = 0; t < 4; ++t) {
#pragma unroll
            for (int p = 0; p < 4; ++p) {
                uint32_t bo_ = SWZ((16*p + (lane & 7) + ((lane & 16) >> 1))*128 + (t*16 + (lane & 8))*2);
                uint32_t kbh[4];
                ldsm4(kbh, kb + AKH + bo_);
#pragma unroll
                for (int mt = 0; mt < 2; ++mt) {
                    mma16816h(sacc[mt][2*p],   fq[mt][t], &kbh[0]);
                    mma16816h(sacc[mt][2*p+1], fq[mt][t], &kbh[2]);
                }
            }
        }

        // causal mask + online softmax (exp2); P -> packed f16; l via ones-MMA
        uint32_t pp[2][8][2];
#pragma unroll
        for (int mt = 0; mt < 2; ++mt) {
            const int rbase = rb0 + 16*mt;
            if (j0 + 63 > rbase) {
#pragma unroll
                for (int nt = 0; nt < 8; ++nt) {
                    int cg = j0 + 8*nt + 2*(lane & 3);
                    if (cg   > rbase)     sacc[mt][nt][0] = -1e30f;
                    if (cg+1 > rbase)     sacc[mt][nt][1] = -1e30f;
                    if (cg   > rbase + 8) sacc[mt][nt][2] = -1e30f;
                    if (cg+1 > rbase + 8) sacc[mt][nt][3] = -1e30f;
                }
            }
            float mx0 = -1e30f, mx1 = -1e30f;
#pragma unroll
            for (int nt = 0; nt < 8; ++nt) {
                mx0 = fmaxf(mx0, fmaxf(sacc[mt][nt][0], sacc[mt][nt][1]));
                mx1 = fmaxf(mx1, fmaxf(sacc[mt][nt][2], sacc[mt][nt][3]));
            }
            mx0 = fmaxf(mx0, __shfl_xor_sync(0xffffffffu, mx0, 1));
            mx0 = fmaxf(mx0, __shfl_xor_sync(0xffffffffu, mx0, 2));
            mx1 = fmaxf(mx1, __shfl_xor_sync(0xffffffffu, mx1, 1));
            mx1 = fmaxf(mx1, __shfl_xor_sync(0xffffffffu, mx1, 2));
            const float mn0 = fmaxf(m[mt][0], mx0), mn1 = fmaxf(m[mt][1], mx1);
            const float c0f = ex2f(m[mt][0] - mn0), c1f = ex2f(m[mt][1] - mn1);
            m[mt][0] = mn0; m[mt][1] = mn1;
#pragma unroll
            for (int nt = 0; nt < 8; ++nt) {
                pp[mt][nt][0] = ex2pack(sacc[mt][nt][0] - mn0, sacc[mt][nt][1] - mn0);
                pp[mt][nt][1] = ex2pack(sacc[mt][nt][2] - mn1, sacc[mt][nt][3] - mn1);
            }
            // rescale running O and l by corr
#pragma unroll
            for (int nt = 0; nt < 8; ++nt) {
                oacc[mt][nt][0] *= c0f; oacc[mt][nt][1] *= c0f;
                oacc[mt][nt][2] *= c1f; oacc[mt][nt][3] *= c1f;
            }
            lacc[mt][0] *= c0f; lacc[mt][1] *= c0f;
            lacc[mt][2] *= c1f; lacc[mt][3] *= c1f;
        }

        // O += P V ; l += P @ ones   (single-pass f16)
#pragma unroll
        for (int kc = 0; kc < 4; ++kc) {
            uint32_t pa0[4] = { pp[0][2*kc][0], pp[0][2*kc][1],
                                pp[0][2*kc+1][0], pp[0][2*kc+1][1] };
            uint32_t pa1[4] = { pp[1][2*kc][0], pp[1][2*kc][1],
                                pp[1][2*kc+1][0], pp[1][2*kc+1][1] };
            mma16816h(lacc[0], pa0, ones_frag);
            mma16816h(lacc[1], pa1, ones_frag);
#pragma unroll
            for (int p = 0; p < 4; ++p) {
                uint32_t vo = SWZ((kc*16 + (lane & 15))*128 + (16*p + ((lane >> 1) & 8))*2);
                uint32_t vbh[4];
                ldsm4t(vbh, kb + AVH + vo);
                mma16816h(oacc[0][2*p],   pa0, &vbh[0]);
                mma16816h(oacc[0][2*p+1], pa0, &vbh[2]);
                mma16816h(oacc[1][2*p],   pa1, &vbh[0]);
                mma16816h(oacc[1][2*p+1], pa1, &vbh[2]);
            }
        }
        __syncthreads();
    }

    // epilogue: l already complete per-thread (cols duplicated), normalize, store
#pragma unroll
    for (int mt = 0; mt < 2; ++mt) {
        const float inv0 = 1.f / lacc[mt][0], inv1 = 1.f / lacc[mt][2];
        const size_t tok = ((size_t)b*SS + rb0 + 16*mt)*DD + h*HDIM;
#pragma unroll
        for (int nt = 0; nt < 8; ++nt) {
            int col = 8*nt + 2*(lane & 3);
            *(uint32_t*)(g_Ch + tok + col)        = pk_h2(oacc[mt][nt][0]*inv0, oacc[mt][nt][1]*inv0);
            *(uint32_t*)(g_Ch + tok + 8*DD + col) = pk_h2(oacc[mt][nt][2]*inv1, oacc[mt][nt][3]*inv1);
        }
    }
}

// ---------------- launch ----------------
extern "C" void kernel_launch(void* const* d_in, const int* in_sizes, int n_in,
                              void* d_out, int out_size)
{
    const float* x  = (const float*)d_in[0];
    const float* Wq = (const float*)d_in[1];
    const float* Wk = (const float*)d_in[2];
    const float* Wv = (const float*)d_in[3];
    const float* Wo = (const float*)d_in[4];
    const float* bo = (const float*)d_in[5];
    float* out = (float*)d_out;
    (void)in_sizes; (void)n_in; (void)out_size;

    static bool attr_done = false;
    if (!attr_done) {
        cudaFuncSetAttribute(qk_hmma,  cudaFuncAttributeMaxDynamicSharedMemorySize, GEMM_SMEM);
        cudaFuncSetAttribute(v_hmma,   cudaFuncAttributeMaxDynamicSharedMemorySize, GEMM_SMEM);
        cudaFuncSetAttribute(out_hmma, cudaFuncAttributeMaxDynamicSharedMemorySize, GEMM_SMEM);
        cudaFuncSetAttribute(attn_hmma, cudaFuncAttributeMaxDynamicSharedMemorySize, ATTN_SMEM);
        attr_done = true;
    }

    split_all<<<(XN4 + 4*WN4) / 256, 256>>>(x, Wq, Wk, Wv, Wo);

    dim3 qk_grid(DD/128, MTOT/128, 2);
    qk_hmma<<<qk_grid, 128, GEMM_SMEM>>>();

    dim3 v_grid(DD/128, MTOT/128, 1);
    v_hmma<<<v_grid, 128, GEMM_SMEM>>>();

    dim3 attn_grid(SS/128, HH, BB);
    attn_hmma<<<attn_grid, 128, ATTN_SMEM>>>();

    dim3 out_grid(DD/128, MTOT/128, 1);
    out_hmma<<<out_grid, 128, GEMM_SMEM>>>(out, bo);
}

// round 15
// speedup vs baseline: 1.5017x; 1.0476x over previous
#include <cuda_runtime.h>
#include <cuda_bf16.h>
#include <cuda_fp16.h>
#include <cstdint>
#include <cstddef>

#define BB 2
#define SS 2048
#define DD 1024
#define HH 16
#define HDIM 64
#define MTOT (BB*SS)   // 4096

// ---------------- device-global scratch ----------------
__device__ __half g_xh[MTOT*DD];                  // x, single f16 (A-side)
__device__ __half g_Wqh[DD*DD], g_Wql[DD*DD];     // Wq/Wk f16 hi/lo (2-pass)
__device__ __half g_Wkh[DD*DD], g_Wkl[DD*DD];
__device__ __half g_Wvh[DD*DD];                   // Wv single f16 (1-pass)
__device__ __half g_Woh[DD*DD];                   // Wo single f16 (1-pass)
__device__ __half g_Qh[MTOT*DD];                  // Q single f16, pre-scaled 0.125*log2(e)
__device__ __half g_Kh[MTOT*DD];                  // K single f16
__device__ __half g_Vh[MTOT*DD];                  // V single f16
__device__ __half g_Ch[MTOT*DD];                  // ctx single f16

// ---------------- helpers ----------------
__device__ __forceinline__ uint32_t smem_u32(const void* p) {
    uint32_t a;
    asm("{ .reg .u64 t; cvta.to.shared.u64 t, %1; cvt.u32.u64 %0, t; }" : "=r"(a) : "l"(p));
    return a;
}
#define SWZ(o)   ((uint32_t)(o) ^ ((((uint32_t)(o)) >> 3) & 0x70))
#define SWZ64(o) ((uint32_t)(o) ^ ((((uint32_t)(o)) >> 3) & 0x30))

__device__ __forceinline__ void cp16(uint32_t d, const void* s) {
    asm volatile("cp.async.cg.shared.global [%0], [%1], 16;" :: "r"(d), "l"(s));
}
#define CP_COMMIT() asm volatile("cp.async.commit_group;" ::: "memory")
#define CP_WAIT1()  asm volatile("cp.async.wait_group 1;" ::: "memory")
#define CP_WAIT0()  asm volatile("cp.async.wait_group 0;" ::: "memory")

__device__ __forceinline__ void ldsm4(uint32_t* r, uint32_t a) {
    asm volatile("ldmatrix.sync.aligned.m8n8.x4.shared.b16 {%0,%1,%2,%3}, [%4];"
        : "=r"(r[0]), "=r"(r[1]), "=r"(r[2]), "=r"(r[3]) : "r"(a));
}
__device__ __forceinline__ void ldsm4t(uint32_t* r, uint32_t a) {
    asm volatile("ldmatrix.sync.aligned.m8n8.x4.trans.shared.b16 {%0,%1,%2,%3}, [%4];"
        : "=r"(r[0]), "=r"(r[1]), "=r"(r[2]), "=r"(r[3]) : "r"(a));
}
__device__ __forceinline__ void mma16816h(float* c, const uint32_t* a, const uint32_t* b) {
    asm volatile("mma.sync.aligned.m16n8k16.row.col.f32.f16.f16.f32 "
        "{%0,%1,%2,%3}, {%4,%5,%6,%7}, {%8,%9}, {%0,%1,%2,%3};"
        : "+f"(c[0]), "+f"(c[1]), "+f"(c[2]), "+f"(c[3])
        : "r"(a[0]), "r"(a[1]), "r"(a[2]), "r"(a[3]), "r"(b[0]), "r"(b[1]));
}

__device__ __forceinline__ uint32_t ex2pack(float lo, float hi) {
    uint32_t d, r;
    asm("cvt.rn.f16x2.f32 %0, %1, %2;" : "=r"(d) : "f"(hi), "f"(lo));
    asm("ex2.approx.f16x2 %0, %1;" : "=r"(r) : "r"(d));
    return r;
}
__device__ __forceinline__ float ex2f(float x) {
    float r; asm("ex2.approx.f32 %0, %1;" : "=f"(r) : "f"(x)); return r;
}

__device__ __forceinline__ uint32_t pk_h2(float v0, float v1) {
    __half2 p; p.x = __float2half_rn(v0); p.y = __float2half_rn(v1);
    return *(uint32_t*)&p;
}
__device__ __forceinline__ void pk_split_h(uint32_t& hi, uint32_t& lo, float v0, float v1) {
    __half hx = __float2half_rn(v0), hy = __float2half_rn(v1);
    __half2 ph; ph.x = hx; ph.y = hy;
    float rx = v0 - __half2float(hx), ry = v1 - __half2float(hy);
    __half2 pl; pl.x = __float2half_rn(rx); pl.y = __float2half_rn(ry);
    hi = *(uint32_t*)&ph;
    lo = *(uint32_t*)&pl;
}

// ---------------- fused fp32 -> f16 split ----------------------------------
#define XN4 (MTOT*DD/4)          // 1048576
#define WN4 (DD*DD/4)            // 262144  (= 1<<18)

__global__ __launch_bounds__(256) void split_all(const float* __restrict__ x,
                                                 const float* __restrict__ Wq,
                                                 const float* __restrict__ Wk,
                                                 const float* __restrict__ Wv,
                                                 const float* __restrict__ Wo)
{
    int i = blockIdx.x * blockDim.x + threadIdx.x;
    if (i < XN4) {
        float4 v = ((const float4*)x)[i];
        ((uint32_t*)g_xh)[i*2+0] = pk_h2(v.x, v.y);
        ((uint32_t*)g_xh)[i*2+1] = pk_h2(v.z, v.w);
        return;
    }
    int j = i - XN4;
    int w = j >> 18;
    int off = j & (WN4 - 1);
    if (w >= 2) {   // Wv / Wo: single f16
        const float* s = (w == 2) ? Wv : Wo;
        __half* hi = (w == 2) ? g_Wvh : g_Woh;
        float4 v = ((const float4*)s)[off];
        ((uint32_t*)hi)[off*2+0] = pk_h2(v.x, v.y);
        ((uint32_t*)hi)[off*2+1] = pk_h2(v.z, v.w);
        return;
    }
    const float* s = (w == 0) ? Wq : Wk;
    __half* hi = (w == 0) ? g_Wqh : g_Wkh;
    __half* lo = (w == 0) ? g_Wql : g_Wkl;
    float4 v = ((const float4*)s)[off];
    uint32_t h0, l0, h1, l1;
    pk_split_h(h0, l0, v.x, v.y);
    pk_split_h(h1, l1, v.z, v.w);
    ((uint32_t*)hi)[off*2+0] = h0; ((uint32_t*)hi)[off*2+1] = h1;
    ((uint32_t*)lo)[off*2+0] = l0; ((uint32_t*)lo)[off*2+1] = l1;
}

// ---------------- f16 HMMA GEMM core (1- or 2-pass B, compile-time) --------
#define SM_A  0u
#define SM_BH 8192u
#define SM_BL 16384u
#define STG   24576u
#define GEMM_SMEM (2*24576)

template<bool TP>
__device__ __forceinline__ void gemm_load(uint32_t sb, int st,
    const __half* __restrict__ A,
    const __half* __restrict__ Bh, const __half* __restrict__ Bl,
    int r0, int c0, int kt, int tid)
{
    const uint32_t base = sb + (uint32_t)st * STG;
#pragma unroll
    for (int i = 0; i < 4; ++i) {
        int idx = tid + i*128;                // 0..511
        int row = idx >> 2, c16 = idx & 3;
        uint32_t so = SWZ64(row*64 + c16*16);
        size_t ga = (size_t)(r0+row)*DD + kt + c16*8;
        size_t gb = (size_t)(c0+row)*DD + kt + c16*8;
        cp16(base + SM_A  + so, A  + ga);
        cp16(base + SM_BH + so, Bh + gb);
        if (TP) cp16(base + SM_BL + so, Bl + gb);
    }
}

template<bool TP>
__device__ __forceinline__ void hgemm_core(const __half* __restrict__ A,
                                           const __half* __restrict__ Bh,
                                           const __half* __restrict__ Bl,
                                           int r0, int c0, float acc[4][8][4])
{
    extern __shared__ char smem[];
    const uint32_t sb = smem_u32(smem);
    const int tid = threadIdx.x, lane = tid & 31, wid = tid >> 5;
    const int wr = wid >> 1, wc = wid & 1;

#pragma unroll
    for (int i = 0; i < 4; ++i)
#pragma unroll
        for (int j = 0; j < 8; ++j)
#pragma unroll
            for (int e = 0; e < 4; ++e) acc[i][j][e] = 0.f;

    const int arow  = 64*wr + (lane & 15);
    const int acol8 = (lane >> 4) * 8;
    const int brow  = 64*wc + (lane & 7) + ((lane & 16) >> 1);
    const int bk8   = lane & 8;

    gemm_load<TP>(sb, 0, A, Bh, Bl, r0, c0, 0, tid);
    CP_COMMIT();

    for (int ch = 0; ch < 32; ++ch) {
        if (ch < 31) {
            gemm_load<TP>(sb, (ch+1) & 1, A, Bh, Bl, r0, c0, (ch+1)*32, tid);
            CP_COMMIT();
            CP_WAIT1();
        } else {
            CP_WAIT0();
        }
        __syncthreads();

        const uint32_t cb = sb + (uint32_t)(ch & 1) * STG;
#pragma unroll
        for (int t = 0; t < 2; ++t) {
            uint32_t fa[4][4], fbh[4][4], fbl[4][4];
#pragma unroll
            for (int mt = 0; mt < 4; ++mt) {
                uint32_t ao = SWZ64((arow + 16*mt)*64 + (t*16 + acol8)*2);
                ldsm4(fa[mt], cb + SM_A + ao);
            }
#pragma unroll
            for (int p = 0; p < 4; ++p) {
                uint32_t bo = SWZ64((brow + 16*p)*64 + (t*16 + bk8)*2);
                ldsm4(fbh[p], cb + SM_BH + bo);
                if (TP) ldsm4(fbl[p], cb + SM_BL + bo);
            }
#pragma unroll
            for (int mt = 0; mt < 4; ++mt)
#pragma unroll
                for (int p = 0; p < 4; ++p) {
                    mma16816h(acc[mt][2*p],   fa[mt], &fbh[p][0]);
                    mma16816h(acc[mt][2*p+1], fa[mt], &fbh[p][2]);
                }
            if (TP) {
#pragma unroll
                for (int mt = 0; mt < 4; ++mt)
#pragma unroll
                    for (int p = 0; p < 4; ++p) {
                        mma16816h(acc[mt][2*p],   fa[mt], &fbl[p][0]);
                        mma16816h(acc[mt][2*p+1], fa[mt], &fbl[p][2]);
                    }
            }
        }
        __syncthreads();
    }
}

// epilogue writer for QKV-style head-layout f16 output
__device__ __forceinline__ void qkv_epilogue(float acc[4][8][4], __half* O,
                                             int r0, int c0, float scale)
{
    const int tid = threadIdx.x, lane = tid & 31, wid = tid >> 5;
    const int wr = wid >> 1, wc = wid & 1;
#pragma unroll
    for (int mt = 0; mt < 4; ++mt)
#pragma unroll
        for (int nt = 0; nt < 8; ++nt) {
            int rg = r0 + 64*wr + 16*mt + (lane >> 2);
            int cg = c0 + 64*wc + 8*nt + 2*(lane & 3);
            int bidx = rg >> 11, s = rg & 2047, h = cg >> 6, hd = cg & 63;
            size_t base = (((size_t)bidx*HH + h)*SS + s)*HDIM + hd;
            *(uint32_t*)(O + base)          = pk_h2(acc[mt][nt][0]*scale, acc[mt][nt][1]*scale);
            *(uint32_t*)(O + base + 8*HDIM) = pk_h2(acc[mt][nt][2]*scale, acc[mt][nt][3]*scale);
        }
}

// Q/K projections: 2-pass split weights
__global__ __launch_bounds__(128, 2) void qk_hmma()
{
    float acc[4][8][4];
    const int r0 = blockIdx.y * 128, c0 = blockIdx.x * 128;
    const bool isQ = (blockIdx.z == 0);
    hgemm_core<true>(g_xh, isQ ? g_Wqh : g_Wkh, isQ ? g_Wql : g_Wkl, r0, c0, acc);
    qkv_epilogue(acc, isQ ? g_Qh : g_Kh, r0, c0, isQ ? 0.18033688f : 1.f);
}

// V projection: single-pass
__global__ __launch_bounds__(128, 2) void v_hmma()
{
    float acc[4][8][4];
    const int r0 = blockIdx.y * 128, c0 = blockIdx.x * 128;
    hgemm_core<false>(g_xh, g_Wvh, nullptr, r0, c0, acc);
    qkv_epilogue(acc, g_Vh, r0, c0, 1.f);
}

__global__ __launch_bounds__(128, 2) void out_hmma(float* __restrict__ out,
                                                   const float* __restrict__ bo)
{
    float acc[4][8][4];
    const int r0 = blockIdx.y * 128, c0 = blockIdx.x * 128;
    hgemm_core<false>(g_Ch, g_Woh, nullptr, r0, c0, acc);

    const int tid = threadIdx.x, lane = tid & 31, wid = tid >> 5;
    const int wr = wid >> 1, wc = wid & 1;
#pragma unroll
    for (int mt = 0; mt < 4; ++mt)
#pragma unroll
        for (int nt = 0; nt < 8; ++nt) {
            int rg = r0 + 64*wr + 16*mt + (lane >> 2);
            int cg = c0 + 64*wc + 8*nt + 2*(lane & 3);
            float b0v = bo[cg], b1v = bo[cg+1];
            float2 o0 = make_float2(acc[mt][nt][0] + b0v, acc[mt][nt][1] + b1v);
            float2 o1 = make_float2(acc[mt][nt][2] + b0v, acc[mt][nt][3] + b1v);
            *(float2*)&out[(size_t)rg * DD + cg] = o0;
            *(float2*)&out[(size_t)(rg+8) * DD + cg] = o1;
        }
}

// ---------------- f16 causal flash attention (64-row q-tiles) --------------
// Q-tile 64 rows, 4 warps x 16 rows. Online softmax (exp2), l via ones-MMA.
// Smem 40KB -> 3 CTAs/SM; balanced causal workload (longest CTA < avg slot load).
#define AQ   0u
#define AKV  8192u
#define KSTG 16384u
#define AKH  0u
#define AVH  8192u
#define ATTN_SMEM (8192 + 2*16384)

__device__ __forceinline__ void attn_load_kv(uint32_t sb, int st, size_t hb, int j0, int tid)
{
    const uint32_t base = sb + AKV + (uint32_t)st * KSTG;
#pragma unroll
    for (int i = 0; i < 4; ++i) {
        int idx = tid + i*128;               // 0..511
        int row = idx >> 3, c16 = idx & 7;
        uint32_t so = SWZ(row*128 + c16*16);
        size_t g = (hb + j0 + row)*HDIM + c16*8;
        cp16(base + AKH + so, g_Kh + g);
        cp16(base + AVH + so, g_Vh + g);
    }
}

__global__ __launch_bounds__(128, 3) void attn_hmma()
{
    extern __shared__ char smem[];
    const uint32_t sb = smem_u32(smem);
    const int tid = threadIdx.x, lane = tid & 31, wid = tid >> 5;
    const int qb = gridDim.x - 1 - blockIdx.x;   // heavy CTAs first
    const int h = blockIdx.y, b = blockIdx.z;
    const int q0 = qb * 64;
    const size_t hb = ((size_t)b*HH + h) * SS;

    // Q tile: 64 x 64 f16 = 8KB
#pragma unroll
    for (int i = 0; i < 4; ++i) {
        int idx = tid + i*128;               // 0..511
        int row = idx >> 3, c16 = idx & 7;
        uint32_t so = SWZ(row*128 + c16*16);
        cp16(sb + AQ + so, g_Qh + (hb + q0 + row)*HDIM + c16*8);
    }
    attn_load_kv(sb, 0, hb, 0, tid);
    CP_COMMIT();

    const uint32_t ones2 = 0x3C003C00u;      // __half2(1,1)
    const uint32_t ones_frag[2] = { ones2, ones2 };

    uint32_t fq[4][4];
    float oacc[8][4];
    float lacc[4];
#pragma unroll
    for (int nt = 0; nt < 8; ++nt)
#pragma unroll
        for (int e = 0; e < 4; ++e) oacc[nt][e] = 0.f;
#pragma unroll
    for (int e = 0; e < 4; ++e) lacc[e] = 0.f;
    float m0 = -1e30f, m1 = -1e30f;

    const int rbase = q0 + 16*wid + (lane >> 2);
    const int ntiles = qb + 1;

    for (int kt = 0; kt < ntiles; ++kt) {
        const int j0 = kt * 64;
        if (kt + 1 < ntiles) {
            attn_load_kv(sb, (kt+1) & 1, hb, j0 + 64, tid);
            CP_COMMIT();
            CP_WAIT1();
        } else {
            CP_WAIT0();
        }
        __syncthreads();

        if (kt == 0) {
#pragma unroll
            for (int t = 0; t < 4; ++t) {
                uint32_t ao = SWZ((16*wid + (lane & 15))*128 + (t*16 + (lane >> 4)*8)*2);
                ldsm4(fq[t], sb + AQ + ao);
            }
        }

        const uint32_t kb = sb + AKV + (uint32_t)(kt & 1) * KSTG;

        // S = Q K^T   (single-pass f16)
        float sacc[8][4];
#pragma unroll
        for (int nt = 0; nt < 8; ++nt)
#pragma unroll
            for (int e = 0; e < 4; ++e) sacc[nt][e] = 0.f;

#pragma unroll
        for (int t = 0; t < 4; ++t) {
#pragma unroll
            for (int p = 0; p < 4; ++p) {
                uint32_t bo_ = SWZ((16*p + (lane & 7) + ((lane & 16) >> 1))*128 + (t*16 + (lane & 8))*2);
                uint32_t kbh[4];
                ldsm4(kbh, kb + AKH + bo_);
                mma16816h(sacc[2*p],   fq[t], &kbh[0]);
                mma16816h(sacc[2*p+1], fq[t], &kbh[2]);
            }
        }

        // causal mask + online softmax (exp2); P -> packed f16; l via ones-MMA
        uint32_t pp[8][2];
        if (j0 + 63 > rbase) {
#pragma unroll
            for (int nt = 0; nt < 8; ++nt) {
                int cg = j0 + 8*nt + 2*(lane & 3);
                if (cg   > rbase)     sacc[nt][0] = -1e30f;
                if (cg+1 > rbase)     sacc[nt][1] = -1e30f;
                if (cg   > rbase + 8) sacc[nt][2] = -1e30f;
                if (cg+1 > rbase + 8) sacc[nt][3] = -1e30f;
            }
        }
        float mx0 = -1e30f, mx1 = -1e30f;
#pragma unroll
        for (int nt = 0; nt < 8; ++nt) {
            mx0 = fmaxf(mx0, fmaxf(sacc[nt][0], sacc[nt][1]));
            mx1 = fmaxf(mx1, fmaxf(sacc[nt][2], sacc[nt][3]));
        }
        mx0 = fmaxf(mx0, __shfl_xor_sync(0xffffffffu, mx0, 1));
        mx0 = fmaxf(mx0, __shfl_xor_sync(0xffffffffu, mx0, 2));
        mx1 = fmaxf(mx1, __shfl_xor_sync(0xffffffffu, mx1, 1));
        mx1 = fmaxf(mx1, __shfl_xor_sync(0xffffffffu, mx1, 2));
        const float mn0 = fmaxf(m0, mx0), mn1 = fmaxf(m1, mx1);
        const float c0f = ex2f(m0 - mn0), c1f = ex2f(m1 - mn1);
        m0 = mn0; m1 = mn1;
#pragma unroll
        for (int nt = 0; nt < 8; ++nt) {
            pp[nt][0] = ex2pack(sacc[nt][0] - mn0, sacc[nt][1] - mn0);
            pp[nt][1] = ex2pack(sacc[nt][2] - mn1, sacc[nt][3] - mn1);
        }
#pragma unroll
        for (int nt = 0; nt < 8; ++nt) {
            oacc[nt][0] *= c0f; oacc[nt][1] *= c0f;
            oacc[nt][2] *= c1f; oacc[nt][3] *= c1f;
        }
        lacc[0] *= c0f; lacc[1] *= c0f;
        lacc[2] *= c1f; lacc[3] *= c1f;

        // O += P V ; l += P @ ones   (single-pass f16)
#pragma unroll
        for (int kc = 0; kc < 4; ++kc) {
            uint32_t pa[4] = { pp[2*kc][0], pp[2*kc][1],
                               pp[2*kc+1][0], pp[2*kc+1][1] };
            mma16816h(lacc, pa, ones_frag);
#pragma unroll
            for (int p = 0; p < 4; ++p) {
                uint32_t vo = SWZ((kc*16 + (lane & 15))*128 + (16*p + ((lane >> 1) & 8))*2);
                uint32_t vbh[4];
                ldsm4t(vbh, kb + AVH + vo);
                mma16816h(oacc[2*p],   pa, &vbh[0]);
                mma16816h(oacc[2*p+1], pa, &vbh[2]);
            }
        }
        __syncthreads();
    }

    // epilogue: normalize, store ctx f16
    const float inv0 = 1.f / lacc[0], inv1 = 1.f / lacc[2];
    const size_t tok = ((size_t)b*SS + rbase)*DD + h*HDIM;
#pragma unroll
    for (int nt = 0; nt < 8; ++nt) {
        int col = 8*nt + 2*(lane & 3);
        *(uint32_t*)(g_Ch + tok + col)        = pk_h2(oacc[nt][0]*inv0, oacc[nt][1]*inv0);
        *(uint32_t*)(g_Ch + tok + 8*DD + col) = pk_h2(oacc[nt][2]*inv1, oacc[nt][3]*inv1);
    }
}

// ---------------- launch ----------------
extern "C" void kernel_launch(void* const* d_in, const int* in_sizes, int n_in,
                              void* d_out, int out_size)
{
    const float* x  = (const float*)d_in[0];
    const float* Wq = (const float*)d_in[1];
    const float* Wk = (const float*)d_in[2];
    const float* Wv = (const float*)d_in[3];
    const float* Wo = (const float*)d_in[4];
    const float* bo = (const float*)d_in[5];
    float* out = (float*)d_out;
    (void)in_sizes; (void)n_in; (void)out_size;

    static bool attr_done = false;
    if (!attr_done) {
        cudaFuncSetAttribute(qk_hmma,  cudaFuncAttributeMaxDynamicSharedMemorySize, GEMM_SMEM);
        cudaFuncSetAttribute(v_hmma,   cudaFuncAttributeMaxDynamicSharedMemorySize, GEMM_SMEM);
        cudaFuncSetAttribute(out_hmma, cudaFuncAttributeMaxDynamicSharedMemorySize, GEMM_SMEM);
        cudaFuncSetAttribute(attn_hmma, cudaFuncAttributeMaxDynamicSharedMemorySize, ATTN_SMEM);
        attr_done = true;
    }

    split_all<<<(XN4 + 4*WN4) / 256, 256>>>(x, Wq, Wk, Wv, Wo);

    dim3 qk_grid(DD/128, MTOT/128, 2);
    qk_hmma<<<qk_grid, 128, GEMM_SMEM>>>();

    dim3 v_grid(DD/128, MTOT/128, 1);
    v_hmma<<<v_grid, 128, GEMM_SMEM>>>();

    dim3 attn_grid(SS/64, HH, BB);
    attn_hmma<<<attn_grid, 128, ATTN_SMEM>>>();

    dim3 out_grid(DD/128, MTOT/128, 1);
    out_hmma<<<out_grid, 128, GEMM_SMEM>>>(out, bo);
}

// round 16
// speedup vs baseline: 1.6932x; 1.1275x over previous
#include <cuda_runtime.h>
#include <cuda_bf16.h>
#include <cuda_fp16.h>
#include <cstdint>
#include <cstddef>

#define BB 2
#define SS 2048
#define DD 1024
#define HH 16
#define HDIM 64
#define MTOT (BB*SS)   // 4096

// ---------------- device-global scratch ----------------
__device__ __half g_xh[MTOT*DD];                  // x, single f16 (A-side)
__device__ __half g_Wqh[DD*DD], g_Wql[DD*DD];     // Wq f16 hi/lo (2-pass)
__device__ __half g_Wkh[DD*DD];                   // Wk single f16 (1-pass)
__device__ __half g_Wvh[DD*DD];                   // Wv single f16 (1-pass)
__device__ __half g_Woh[DD*DD];                   // Wo single f16 (1-pass)
__device__ __half g_Qh[MTOT*DD];                  // Q single f16, pre-scaled 0.125*log2(e)
__device__ __half g_Kh[MTOT*DD];                  // K single f16
__device__ __half g_Vh[MTOT*DD];                  // V single f16
__device__ __half g_Ch[MTOT*DD];                  // ctx single f16

// ---------------- helpers ----------------
__device__ __forceinline__ uint32_t smem_u32(const void* p) {
    uint32_t a;
    asm("{ .reg .u64 t; cvta.to.shared.u64 t, %1; cvt.u32.u64 %0, t; }" : "=r"(a) : "l"(p));
    return a;
}
#define SWZ(o)   ((uint32_t)(o) ^ ((((uint32_t)(o)) >> 3) & 0x70))
#define SWZ64(o) ((uint32_t)(o) ^ ((((uint32_t)(o)) >> 3) & 0x30))

__device__ __forceinline__ void cp16(uint32_t d, const void* s) {
    asm volatile("cp.async.cg.shared.global [%0], [%1], 16;" :: "r"(d), "l"(s));
}
#define CP_COMMIT() asm volatile("cp.async.commit_group;" ::: "memory")
#define CP_WAIT1()  asm volatile("cp.async.wait_group 1;" ::: "memory")
#define CP_WAIT0()  asm volatile("cp.async.wait_group 0;" ::: "memory")

__device__ __forceinline__ void ldsm4(uint32_t* r, uint32_t a) {
    asm volatile("ldmatrix.sync.aligned.m8n8.x4.shared.b16 {%0,%1,%2,%3}, [%4];"
        : "=r"(r[0]), "=r"(r[1]), "=r"(r[2]), "=r"(r[3]) : "r"(a));
}
__device__ __forceinline__ void ldsm4t(uint32_t* r, uint32_t a) {
    asm volatile("ldmatrix.sync.aligned.m8n8.x4.trans.shared.b16 {%0,%1,%2,%3}, [%4];"
        : "=r"(r[0]), "=r"(r[1]), "=r"(r[2]), "=r"(r[3]) : "r"(a));
}
__device__ __forceinline__ void mma16816h(float* c, const uint32_t* a, const uint32_t* b) {
    asm volatile("mma.sync.aligned.m16n8k16.row.col.f32.f16.f16.f32 "
        "{%0,%1,%2,%3}, {%4,%5,%6,%7}, {%8,%9}, {%0,%1,%2,%3};"
        : "+f"(c[0]), "+f"(c[1]), "+f"(c[2]), "+f"(c[3])
        : "r"(a[0]), "r"(a[1]), "r"(a[2]), "r"(a[3]), "r"(b[0]), "r"(b[1]));
}

__device__ __forceinline__ uint32_t ex2pack(float lo, float hi) {
    uint32_t d, r;
    asm("cvt.rn.f16x2.f32 %0, %1, %2;" : "=r"(d) : "f"(hi), "f"(lo));
    asm("ex2.approx.f16x2 %0, %1;" : "=r"(r) : "r"(d));
    return r;
}
__device__ __forceinline__ float ex2f(float x) {
    float r; asm("ex2.approx.f32 %0, %1;" : "=f"(r) : "f"(x)); return r;
}

__device__ __forceinline__ uint32_t pk_h2(float v0, float v1) {
    __half2 p; p.x = __float2half_rn(v0); p.y = __float2half_rn(v1);
    return *(uint32_t*)&p;
}
__device__ __forceinline__ void pk_split_h(uint32_t& hi, uint32_t& lo, float v0, float v1) {
    __half hx = __float2half_rn(v0), hy = __float2half_rn(v1);
    __half2 ph; ph.x = hx; ph.y = hy;
    float rx = v0 - __half2float(hx), ry = v1 - __half2float(hy);
    __half2 pl; pl.x = __float2half_rn(rx); pl.y = __float2half_rn(ry);
    hi = *(uint32_t*)&ph;
    lo = *(uint32_t*)&pl;
}

// ---------------- fused fp32 -> f16 split ----------------------------------
#define XN4 (MTOT*DD/4)          // 1048576
#define WN4 (DD*DD/4)            // 262144  (= 1<<18)

__global__ __launch_bounds__(256) void split_all(const float* __restrict__ x,
                                                 const float* __restrict__ Wq,
                                                 const float* __restrict__ Wk,
                                                 const float* __restrict__ Wv,
                                                 const float* __restrict__ Wo)
{
    int i = blockIdx.x * blockDim.x + threadIdx.x;
    if (i < XN4) {
        float4 v = ((const float4*)x)[i];
        ((uint32_t*)g_xh)[i*2+0] = pk_h2(v.x, v.y);
        ((uint32_t*)g_xh)[i*2+1] = pk_h2(v.z, v.w);
        return;
    }
    int j = i - XN4;
    int w = j >> 18;
    int off = j & (WN4 - 1);
    if (w >= 1) {   // Wk / Wv / Wo: single f16
        const float* s = (w == 1) ? Wk : (w == 2) ? Wv : Wo;
        __half* hi = (w == 1) ? g_Wkh : (w == 2) ? g_Wvh : g_Woh;
        float4 v = ((const float4*)s)[off];
        ((uint32_t*)hi)[off*2+0] = pk_h2(v.x, v.y);
        ((uint32_t*)hi)[off*2+1] = pk_h2(v.z, v.w);
        return;
    }
    // Wq: 2-way split
    float4 v = ((const float4*)Wq)[off];
    uint32_t h0, l0, h1, l1;
    pk_split_h(h0, l0, v.x, v.y);
    pk_split_h(h1, l1, v.z, v.w);
    ((uint32_t*)g_Wqh)[off*2+0] = h0; ((uint32_t*)g_Wqh)[off*2+1] = h1;
    ((uint32_t*)g_Wql)[off*2+0] = l0; ((uint32_t*)g_Wql)[off*2+1] = l1;
}

// ---------------- f16 HMMA GEMM core (1- or 2-pass B, compile-time) --------
#define SM_A  0u
#define SM_BH 8192u
#define SM_BL 16384u
#define STG   24576u
#define GEMM_SMEM (2*24576)

template<bool TP>
__device__ __forceinline__ void gemm_load(uint32_t sb, int st,
    const __half* __restrict__ A,
    const __half* __restrict__ Bh, const __half* __restrict__ Bl,
    int r0, int c0, int kt, int tid)
{
    const uint32_t base = sb + (uint32_t)st * STG;
#pragma unroll
    for (int i = 0; i < 4; ++i) {
        int idx = tid + i*128;                // 0..511
        int row = idx >> 2, c16 = idx & 3;
        uint32_t so = SWZ64(row*64 + c16*16);
        size_t ga = (size_t)(r0+row)*DD + kt + c16*8;
        size_t gb = (size_t)(c0+row)*DD + kt + c16*8;
        cp16(base + SM_A  + so, A  + ga);
        cp16(base + SM_BH + so, Bh + gb);
        if (TP) cp16(base + SM_BL + so, Bl + gb);
    }
}

template<bool TP>
__device__ __forceinline__ void hgemm_core(const __half* __restrict__ A,
                                           const __half* __restrict__ Bh,
                                           const __half* __restrict__ Bl,
                                           int r0, int c0, float acc[4][8][4])
{
    extern __shared__ char smem[];
    const uint32_t sb = smem_u32(smem);
    const int tid = threadIdx.x, lane = tid & 31, wid = tid >> 5;
    const int wr = wid >> 1, wc = wid & 1;

#pragma unroll
    for (int i = 0; i < 4; ++i)
#pragma unroll
        for (int j = 0; j < 8; ++j)
#pragma unroll
            for (int e = 0; e < 4; ++e) acc[i][j][e] = 0.f;

    const int arow  = 64*wr + (lane & 15);
    const int acol8 = (lane >> 4) * 8;
    const int brow  = 64*wc + (lane & 7) + ((lane & 16) >> 1);
    const int bk8   = lane & 8;

    gemm_load<TP>(sb, 0, A, Bh, Bl, r0, c0, 0, tid);
    CP_COMMIT();

    for (int ch = 0; ch < 32; ++ch) {
        if (ch < 31) {
            gemm_load<TP>(sb, (ch+1) & 1, A, Bh, Bl, r0, c0, (ch+1)*32, tid);
            CP_COMMIT();
            CP_WAIT1();
        } else {
            CP_WAIT0();
        }
        __syncthreads();

        const uint32_t cb = sb + (uint32_t)(ch & 1) * STG;
#pragma unroll
        for (int t = 0; t < 2; ++t) {
            uint32_t fa[4][4], fbh[4][4], fbl[4][4];
#pragma unroll
            for (int mt = 0; mt < 4; ++mt) {
                uint32_t ao = SWZ64((arow + 16*mt)*64 + (t*16 + acol8)*2);
                ldsm4(fa[mt], cb + SM_A + ao);
            }
#pragma unroll
            for (int p = 0; p < 4; ++p) {
                uint32_t bo = SWZ64((brow + 16*p)*64 + (t*16 + bk8)*2);
                ldsm4(fbh[p], cb + SM_BH + bo);
                if (TP) ldsm4(fbl[p], cb + SM_BL + bo);
            }
#pragma unroll
            for (int mt = 0; mt < 4; ++mt)
#pragma unroll
                for (int p = 0; p < 4; ++p) {
                    mma16816h(acc[mt][2*p],   fa[mt], &fbh[p][0]);
                    mma16816h(acc[mt][2*p+1], fa[mt], &fbh[p][2]);
                }
            if (TP) {
#pragma unroll
                for (int mt = 0; mt < 4; ++mt)
#pragma unroll
                    for (int p = 0; p < 4; ++p) {
                        mma16816h(acc[mt][2*p],   fa[mt], &fbl[p][0]);
                        mma16816h(acc[mt][2*p+1], fa[mt], &fbl[p][2]);
                    }
            }
        }
        __syncthreads();
    }
}

// epilogue writer for QKV-style head-layout f16 output
__device__ __forceinline__ void qkv_epilogue(float acc[4][8][4], __half* O,
                                             int r0, int c0, float scale)
{
    const int tid = threadIdx.x, lane = tid & 31, wid = tid >> 5;
    const int wr = wid >> 1, wc = wid & 1;
#pragma unroll
    for (int mt = 0; mt < 4; ++mt)
#pragma unroll
        for (int nt = 0; nt < 8; ++nt) {
            int rg = r0 + 64*wr + 16*mt + (lane >> 2);
            int cg = c0 + 64*wc + 8*nt + 2*(lane & 3);
            int bidx = rg >> 11, s = rg & 2047, h = cg >> 6, hd = cg & 63;
            size_t base = (((size_t)bidx*HH + h)*SS + s)*HDIM + hd;
            *(uint32_t*)(O + base)          = pk_h2(acc[mt][nt][0]*scale, acc[mt][nt][1]*scale);
            *(uint32_t*)(O + base + 8*HDIM) = pk_h2(acc[mt][nt][2]*scale, acc[mt][nt][3]*scale);
        }
}

// Q projection: 2-pass split weights (only <true> instantiated here)
__global__ __launch_bounds__(128, 2) void q_hmma()
{
    float acc[4][8][4];
    const int r0 = blockIdx.y * 128, c0 = blockIdx.x * 128;
    hgemm_core<true>(g_xh, g_Wqh, g_Wql, r0, c0, acc);
    qkv_epilogue(acc, g_Qh, r0, c0, 0.18033688f);   // 0.125*log2(e)
}

// K/V projections: single-pass, pointer-select on z (one instantiation)
__global__ __launch_bounds__(128, 2) void kv_hmma()
{
    float acc[4][8][4];
    const int r0 = blockIdx.y * 128, c0 = blockIdx.x * 128;
    const bool isV = (blockIdx.z != 0);
    hgemm_core<false>(g_xh, isV ? g_Wvh : g_Wkh, nullptr, r0, c0, acc);
    qkv_epilogue(acc, isV ? g_Vh : g_Kh, r0, c0, 1.f);
}

__global__ __launch_bounds__(128, 2) void out_hmma(float* __restrict__ out,
                                                   const float* __restrict__ bo)
{
    float acc[4][8][4];
    const int r0 = blockIdx.y * 128, c0 = blockIdx.x * 128;
    hgemm_core<false>(g_Ch, g_Woh, nullptr, r0, c0, acc);

    const int tid = threadIdx.x, lane = tid & 31, wid = tid >> 5;
    const int wr = wid >> 1, wc = wid & 1;
#pragma unroll
    for (int mt = 0; mt < 4; ++mt)
#pragma unroll
        for (int nt = 0; nt < 8; ++nt) {
            int rg = r0 + 64*wr + 16*mt + (lane >> 2);
            int cg = c0 + 64*wc + 8*nt + 2*(lane & 3);
            float b0v = bo[cg], b1v = bo[cg+1];
            float2 o0 = make_float2(acc[mt][nt][0] + b0v, acc[mt][nt][1] + b1v);
            float2 o1 = make_float2(acc[mt][nt][2] + b0v, acc[mt][nt][3] + b1v);
            *(float2*)&out[(size_t)rg * DD + cg] = o0;
            *(float2*)&out[(size_t)(rg+8) * DD + cg] = o1;
        }
}

// ---------------- f16 causal flash attention (64-row q-tiles) --------------
#define AQ   0u
#define AKV  8192u
#define KSTG 16384u
#define AKH  0u
#define AVH  8192u
#define ATTN_SMEM (8192 + 2*16384)

__device__ __forceinline__ void attn_load_kv(uint32_t sb, int st, size_t hb, int j0, int tid)
{
    const uint32_t base = sb + AKV + (uint32_t)st * KSTG;
#pragma unroll
    for (int i = 0; i < 4; ++i) {
        int idx = tid + i*128;               // 0..511
        int row = idx >> 3, c16 = idx & 7;
        uint32_t so = SWZ(row*128 + c16*16);
        size_t g = (hb + j0 + row)*HDIM + c16*8;
        cp16(base + AKH + so, g_Kh + g);
        cp16(base + AVH + so, g_Vh + g);
    }
}

__global__ __launch_bounds__(128, 3) void attn_hmma()
{
    extern __shared__ char smem[];
    const uint32_t sb = smem_u32(smem);
    const int tid = threadIdx.x, lane = tid & 31, wid = tid >> 5;
    const int qb = gridDim.x - 1 - blockIdx.x;   // heavy CTAs first
    const int h = blockIdx.y, b = blockIdx.z;
    const int q0 = qb * 64;
    const size_t hb = ((size_t)b*HH + h) * SS;

    // Q tile: 64 x 64 f16 = 8KB
#pragma unroll
    for (int i = 0; i < 4; ++i) {
        int idx = tid + i*128;               // 0..511
        int row = idx >> 3, c16 = idx & 7;
        uint32_t so = SWZ(row*128 + c16*16);
        cp16(sb + AQ + so, g_Qh + (hb + q0 + row)*HDIM + c16*8);
    }
    attn_load_kv(sb, 0, hb, 0, tid);
    CP_COMMIT();

    const uint32_t ones2 = 0x3C003C00u;      // __half2(1,1)
    const uint32_t ones_frag[2] = { ones2, ones2 };

    uint32_t fq[4][4];
    float oacc[8][4];
    float lacc[4];
#pragma unroll
    for (int nt = 0; nt < 8; ++nt)
#pragma unroll
        for (int e = 0; e < 4; ++e) oacc[nt][e] = 0.f;
#pragma unroll
    for (int e = 0; e < 4; ++e) lacc[e] = 0.f;
    float m0 = -1e30f, m1 = -1e30f;

    const int rbase = q0 + 16*wid + (lane >> 2);
    const int ntiles = qb + 1;

    for (int kt = 0; kt < ntiles; ++kt) {
        const int j0 = kt * 64;
        if (kt + 1 < ntiles) {
            attn_load_kv(sb, (kt+1) & 1, hb, j0 + 64, tid);
            CP_COMMIT();
            CP_WAIT1();
        } else {
            CP_WAIT0();
        }
        __syncthreads();

        if (kt == 0) {
#pragma unroll
            for (int t = 0; t < 4; ++t) {
                uint32_t ao = SWZ((16*wid + (lane & 15))*128 + (t*16 + (lane >> 4)*8)*2);
                ldsm4(fq[t], sb + AQ + ao);
            }
        }

        const uint32_t kb = sb + AKV + (uint32_t)(kt & 1) * KSTG;

        // S = Q K^T   (single-pass f16)
        float sacc[8][4];
#pragma unroll
        for (int nt = 0; nt < 8; ++nt)
#pragma unroll
            for (int e = 0; e < 4; ++e) sacc[nt][e] = 0.f;

#pragma unroll
        for (int t = 0; t < 4; ++t) {
#pragma unroll
            for (int p = 0; p < 4; ++p) {
                uint32_t bo_ = SWZ((16*p + (lane & 7) + ((lane & 16) >> 1))*128 + (t*16 + (lane & 8))*2);
                uint32_t kbh[4];
                ldsm4(kbh, kb + AKH + bo_);
                mma16816h(sacc[2*p],   fq[t], &kbh[0]);
                mma16816h(sacc[2*p+1], fq[t], &kbh[2]);
            }
        }

        // causal mask + online softmax (exp2); P -> packed f16; l via ones-MMA
        uint32_t pp[8][2];
        if (j0 + 63 > rbase) {
#pragma unroll
            for (int nt = 0; nt < 8; ++nt) {
                int cg = j0 + 8*nt + 2*(lane & 3);
                if (cg   > rbase)     sacc[nt][0] = -1e30f;
                if (cg+1 > rbase)     sacc[nt][1] = -1e30f;
                if (cg   > rbase + 8) sacc[nt][2] = -1e30f;
                if (cg+1 > rbase + 8) sacc[nt][3] = -1e30f;
            }
        }
        float mx0 = -1e30f, mx1 = -1e30f;
#pragma unroll
        for (int nt = 0; nt < 8; ++nt) {
            mx0 = fmaxf(mx0, fmaxf(sacc[nt][0], sacc[nt][1]));
            mx1 = fmaxf(mx1, fmaxf(sacc[nt][2], sacc[nt][3]));
        }
        mx0 = fmaxf(mx0, __shfl_xor_sync(0xffffffffu, mx0, 1));
        mx0 = fmaxf(mx0, __shfl_xor_sync(0xffffffffu, mx0, 2));
        mx1 = fmaxf(mx1, __shfl_xor_sync(0xffffffffu, mx1, 1));
        mx1 = fmaxf(mx1, __shfl_xor_sync(0xffffffffu, mx1, 2));
        const float mn0 = fmaxf(m0, mx0), mn1 = fmaxf(m1, mx1);
        const float c0f = ex2f(m0 - mn0), c1f = ex2f(m1 - mn1);
        m0 = mn0; m1 = mn1;
#pragma unroll
        for (int nt = 0; nt < 8; ++nt) {
            pp[nt][0] = ex2pack(sacc[nt][0] - mn0, sacc[nt][1] - mn0);
            pp[nt][1] = ex2pack(sacc[nt][2] - mn1, sacc[nt][3] - mn1);
        }
#pragma unroll
        for (int nt = 0; nt < 8; ++nt) {
            oacc[nt][0] *= c0f; oacc[nt][1] *= c0f;
            oacc[nt][2] *= c1f; oacc[nt][3] *= c1f;
        }
        lacc[0] *= c0f; lacc[1] *= c0f;
        lacc[2] *= c1f; lacc[3] *= c1f;

        // O += P V ; l += P @ ones   (single-pass f16)
#pragma unroll
        for (int kc = 0; kc < 4; ++kc) {
            uint32_t pa[4] = { pp[2*kc][0], pp[2*kc][1],
                               pp[2*kc+1][0], pp[2*kc+1][1] };
            mma16816h(lacc, pa, ones_frag);
#pragma unroll
            for (int p = 0; p < 4; ++p) {
                uint32_t vo = SWZ((kc*16 + (lane & 15))*128 + (16*p + ((lane >> 1) & 8))*2);
                uint32_t vbh[4];
                ldsm4t(vbh, kb + AVH + vo);
                mma16816h(oacc[2*p],   pa, &vbh[0]);
                mma16816h(oacc[2*p+1], pa, &vbh[2]);
            }
        }
        __syncthreads();
    }

    // epilogue: normalize, store ctx f16
    const float inv0 = 1.f / lacc[0], inv1 = 1.f / lacc[2];
    const size_t tok = ((size_t)b*SS + rbase)*DD + h*HDIM;
#pragma unroll
    for (int nt = 0; nt < 8; ++nt) {
        int col = 8*nt + 2*(lane & 3);
        *(uint32_t*)(g_Ch + tok + col)        = pk_h2(oacc[nt][0]*inv0, oacc[nt][1]*inv0);
        *(uint32_t*)(g_Ch + tok + 8*DD + col) = pk_h2(oacc[nt][2]*inv1, oacc[nt][3]*inv1);
    }
}

// ---------------- launch ----------------
extern "C" void kernel_launch(void* const* d_in, const int* in_sizes, int n_in,
                              void* d_out, int out_size)
{
    const float* x  = (const float*)d_in[0];
    const float* Wq = (const float*)d_in[1];
    const float* Wk = (const float*)d_in[2];
    const float* Wv = (const float*)d_in[3];
    const float* Wo = (const float*)d_in[4];
    const float* bo = (const float*)d_in[5];
    float* out = (float*)d_out;
    (void)in_sizes; (void)n_in; (void)out_size;

    static bool attr_done = false;
    if (!attr_done) {
        cudaFuncSetAttribute(q_hmma,   cudaFuncAttributeMaxDynamicSharedMemorySize, GEMM_SMEM);
        cudaFuncSetAttribute(kv_hmma,  cudaFuncAttributeMaxDynamicSharedMemorySize, GEMM_SMEM);
        cudaFuncSetAttribute(out_hmma, cudaFuncAttributeMaxDynamicSharedMemorySize, GEMM_SMEM);
        cudaFuncSetAttribute(attn_hmma, cudaFuncAttributeMaxDynamicSharedMemorySize, ATTN_SMEM);
        attr_done = true;
    }

    split_all<<<(XN4 + 4*WN4) / 256, 256>>>(x, Wq, Wk, Wv, Wo);

    dim3 q_grid(DD/128, MTOT/128, 1);
    q_hmma<<<q_grid, 128, GEMM_SMEM>>>();

    dim3 kv_grid(DD/128, MTOT/128, 2);
    kv_hmma<<<kv_grid, 128, GEMM_SMEM>>>();

    dim3 attn_grid(SS/64, HH, BB);
    attn_hmma<<<attn_grid, 128, ATTN_SMEM>>>();

    dim3 out_grid(DD/128, MTOT/128, 1);
    out_hmma<<<out_grid, 128, GEMM_SMEM>>>(out, bo);
}

// round 17
// speedup vs baseline: 1.9409x; 1.1463x over previous
#include <cuda_runtime.h>
#include <cuda_bf16.h>
#include <cuda_fp16.h>
#include <cstdint>
#include <cstddef>

#define BB 2
#define SS 2048
#define DD 1024
#define HH 16
#define HDIM 64
#define MTOT (BB*SS)   // 4096

// ---------------- device-global scratch ----------------
__device__ __half g_xh[MTOT*DD];                  // x, single f16
__device__ __half g_Wqh[DD*DD];                   // all weights single f16 now
__device__ __half g_Wkh[DD*DD];
__device__ __half g_Wvh[DD*DD];
__device__ __half g_Woh[DD*DD];
__device__ __half g_Qh[MTOT*DD];                  // Q f16, pre-scaled 0.125*log2(e)
__device__ __half g_Kh[MTOT*DD];
__device__ __half g_Vh[MTOT*DD];
__device__ __half g_Ch[MTOT*DD];                  // ctx f16

// ---------------- helpers ----------------
__device__ __forceinline__ uint32_t smem_u32(const void* p) {
    uint32_t a;
    asm("{ .reg .u64 t; cvta.to.shared.u64 t, %1; cvt.u32.u64 %0, t; }" : "=r"(a) : "l"(p));
    return a;
}
#define SWZ(o)   ((uint32_t)(o) ^ ((((uint32_t)(o)) >> 3) & 0x70))
#define SWZ64(o) ((uint32_t)(o) ^ ((((uint32_t)(o)) >> 3) & 0x30))

__device__ __forceinline__ void cp16(uint32_t d, const void* s) {
    asm volatile("cp.async.cg.shared.global [%0], [%1], 16;" :: "r"(d), "l"(s));
}
#define CP_COMMIT() asm volatile("cp.async.commit_group;" ::: "memory")
#define CP_WAIT1()  asm volatile("cp.async.wait_group 1;" ::: "memory")
#define CP_WAIT0()  asm volatile("cp.async.wait_group 0;" ::: "memory")

__device__ __forceinline__ void ldsm4(uint32_t* r, uint32_t a) {
    asm volatile("ldmatrix.sync.aligned.m8n8.x4.shared.b16 {%0,%1,%2,%3}, [%4];"
        : "=r"(r[0]), "=r"(r[1]), "=r"(r[2]), "=r"(r[3]) : "r"(a));
}
__device__ __forceinline__ void ldsm4t(uint32_t* r, uint32_t a) {
    asm volatile("ldmatrix.sync.aligned.m8n8.x4.trans.shared.b16 {%0,%1,%2,%3}, [%4];"
        : "=r"(r[0]), "=r"(r[1]), "=r"(r[2]), "=r"(r[3]) : "r"(a));
}
__device__ __forceinline__ void mma16816h(float* c, const uint32_t* a, const uint32_t* b) {
    asm volatile("mma.sync.aligned.m16n8k16.row.col.f32.f16.f16.f32 "
        "{%0,%1,%2,%3}, {%4,%5,%6,%7}, {%8,%9}, {%0,%1,%2,%3};"
        : "+f"(c[0]), "+f"(c[1]), "+f"(c[2]), "+f"(c[3])
        : "r"(a[0]), "r"(a[1]), "r"(a[2]), "r"(a[3]), "r"(b[0]), "r"(b[1]));
}

__device__ __forceinline__ uint32_t ex2pack(float lo, float hi) {
    uint32_t d, r;
    asm("cvt.rn.f16x2.f32 %0, %1, %2;" : "=r"(d) : "f"(hi), "f"(lo));
    asm("ex2.approx.f16x2 %0, %1;" : "=r"(r) : "r"(d));
    return r;
}
__device__ __forceinline__ float ex2f(float x) {
    float r; asm("ex2.approx.f32 %0, %1;" : "=f"(r) : "f"(x)); return r;
}

__device__ __forceinline__ uint32_t pk_h2(float v0, float v1) {
    __half2 p; p.x = __float2half_rn(v0); p.y = __float2half_rn(v1);
    return *(uint32_t*)&p;
}

// ---------------- fused fp32 -> f16 cast (x + 4 weights, all single) --------
#define XN4 (MTOT*DD/4)          // 1048576
#define WN4 (DD*DD/4)            // 262144  (= 1<<18)

__global__ __launch_bounds__(256) void split_all(const float* __restrict__ x,
                                                 const float* __restrict__ Wq,
                                                 const float* __restrict__ Wk,
                                                 const float* __restrict__ Wv,
                                                 const float* __restrict__ Wo)
{
    int i = blockIdx.x * blockDim.x + threadIdx.x;
    const float* s;
    __half* dst;
    int off;
    if (i < XN4) { s = x; dst = g_xh; off = i; }
    else {
        int j = i - XN4;
        int w = j >> 18;
        off = j & (WN4 - 1);
        if (w == 0)      { s = Wq; dst = g_Wqh; }
        else if (w == 1) { s = Wk; dst = g_Wkh; }
        else if (w == 2) { s = Wv; dst = g_Wvh; }
        else             { s = Wo; dst = g_Woh; }
    }
    float4 v = ((const float4*)s)[off];
    ((uint32_t*)dst)[off*2+0] = pk_h2(v.x, v.y);
    ((uint32_t*)dst)[off*2+1] = pk_h2(v.z, v.w);
}

// ---------------- f16 single-pass HMMA GEMM core ---------------------------
// CTA tile 128x128, 128 threads (2x2 warps, 64x64/warp), K-chunk 32 (SW64),
// 2-stage cp.async, 2 CTAs/SM.
#define SM_A  0u
#define SM_BH 8192u
#define STG   16384u
#define GEMM_SMEM (2*16384)

__device__ __forceinline__ void gemm_load(uint32_t sb, int st,
    const __half* __restrict__ A, const __half* __restrict__ Bh,
    int r0, int c0, int kt, int tid)
{
    const uint32_t base = sb + (uint32_t)st * STG;
#pragma unroll
    for (int i = 0; i < 4; ++i) {
        int idx = tid + i*128;                // 0..511
        int row = idx >> 2, c16 = idx & 3;
        uint32_t so = SWZ64(row*64 + c16*16);
        size_t ga = (size_t)(r0+row)*DD + kt + c16*8;
        size_t gb = (size_t)(c0+row)*DD + kt + c16*8;
        cp16(base + SM_A  + so, A  + ga);
        cp16(base + SM_BH + so, Bh + gb);
    }
}

__device__ __forceinline__ void hgemm_core(const __half* __restrict__ A,
                                           const __half* __restrict__ Bh,
                                           int r0, int c0, float acc[4][8][4])
{
    extern __shared__ char smem[];
    const uint32_t sb = smem_u32(smem);
    const int tid = threadIdx.x, lane = tid & 31, wid = tid >> 5;
    const int wr = wid >> 1, wc = wid & 1;

#pragma unroll
    for (int i = 0; i < 4; ++i)
#pragma unroll
        for (int j = 0; j < 8; ++j)
#pragma unroll
            for (int e = 0; e < 4; ++e) acc[i][j][e] = 0.f;

    const int arow  = 64*wr + (lane & 15);
    const int acol8 = (lane >> 4) * 8;
    const int brow  = 64*wc + (lane & 7) + ((lane & 16) >> 1);
    const int bk8   = lane & 8;

    gemm_load(sb, 0, A, Bh, r0, c0, 0, tid);
    CP_COMMIT();

    for (int ch = 0; ch < 32; ++ch) {
        if (ch < 31) {
            gemm_load(sb, (ch+1) & 1, A, Bh, r0, c0, (ch+1)*32, tid);
            CP_COMMIT();
            CP_WAIT1();
        } else {
            CP_WAIT0();
        }
        __syncthreads();

        const uint32_t cb = sb + (uint32_t)(ch & 1) * STG;
#pragma unroll
        for (int t = 0; t < 2; ++t) {
            uint32_t fa[4][4], fbh[4][4];
#pragma unroll
            for (int mt = 0; mt < 4; ++mt) {
                uint32_t ao = SWZ64((arow + 16*mt)*64 + (t*16 + acol8)*2);
                ldsm4(fa[mt], cb + SM_A + ao);
            }
#pragma unroll
            for (int p = 0; p < 4; ++p) {
                uint32_t bo = SWZ64((brow + 16*p)*64 + (t*16 + bk8)*2);
                ldsm4(fbh[p], cb + SM_BH + bo);
            }
#pragma unroll
            for (int mt = 0; mt < 4; ++mt)
#pragma unroll
                for (int p = 0; p < 4; ++p) {
                    mma16816h(acc[mt][2*p],   fa[mt], &fbh[p][0]);
                    mma16816h(acc[mt][2*p+1], fa[mt], &fbh[p][2]);
                }
        }
        __syncthreads();
    }
}

// epilogue writer for QKV-style head-layout f16 output
__device__ __forceinline__ void qkv_epilogue(float acc[4][8][4], __half* O,
                                             int r0, int c0, float scale)
{
    const int tid = threadIdx.x, lane = tid & 31, wid = tid >> 5;
    const int wr = wid >> 1, wc = wid & 1;
#pragma unroll
    for (int mt = 0; mt < 4; ++mt)
#pragma unroll
        for (int nt = 0; nt < 8; ++nt) {
            int rg = r0 + 64*wr + 16*mt + (lane >> 2);
            int cg = c0 + 64*wc + 8*nt + 2*(lane & 3);
            int bidx = rg >> 11, s = rg & 2047, h = cg >> 6, hd = cg & 63;
            size_t base = (((size_t)bidx*HH + h)*SS + s)*HDIM + hd;
            *(uint32_t*)(O + base)          = pk_h2(acc[mt][nt][0]*scale, acc[mt][nt][1]*scale);
            *(uint32_t*)(O + base + 8*HDIM) = pk_h2(acc[mt][nt][2]*scale, acc[mt][nt][3]*scale);
        }
}

// Merged Q/K/V projections: single-pass, pointer-select on z
__global__ __launch_bounds__(128, 2) void qkv_hmma()
{
    float acc[4][8][4];
    const int r0 = blockIdx.y * 128, c0 = blockIdx.x * 128;
    const int z = blockIdx.z;
    const __half* W = (z == 0) ? g_Wqh : (z == 1) ? g_Wkh : g_Wvh;
    hgemm_core(g_xh, W, r0, c0, acc);
    __half* O = (z == 0) ? g_Qh : (z == 1) ? g_Kh : g_Vh;
    qkv_epilogue(acc, O, r0, c0, (z == 0) ? 0.18033688f : 1.f);  // 0.125*log2(e)
}

__global__ __launch_bounds__(128, 2) void out_hmma(float* __restrict__ out,
                                                   const float* __restrict__ bo)
{
    float acc[4][8][4];
    const int r0 = blockIdx.y * 128, c0 = blockIdx.x * 128;
    hgemm_core(g_Ch, g_Woh, r0, c0, acc);

    const int tid = threadIdx.x, lane = tid & 31, wid = tid >> 5;
    const int wr = wid >> 1, wc = wid & 1;
#pragma unroll
    for (int mt = 0; mt < 4; ++mt)
#pragma unroll
        for (int nt = 0; nt < 8; ++nt) {
            int rg = r0 + 64*wr + 16*mt + (lane >> 2);
            int cg = c0 + 64*wc + 8*nt + 2*(lane & 3);
            float b0v = bo[cg], b1v = bo[cg+1];
            float2 o0 = make_float2(acc[mt][nt][0] + b0v, acc[mt][nt][1] + b1v);
            float2 o1 = make_float2(acc[mt][nt][2] + b0v, acc[mt][nt][3] + b1v);
            *(float2*)&out[(size_t)rg * DD + cg] = o0;
            *(float2*)&out[(size_t)(rg+8) * DD + cg] = o1;
        }
}

// ---------------- f16 causal flash attention (64-row q-tiles) --------------
// Online softmax (exp2), l via ones-MMA, ballot-gated rescale.
#define AQ   0u
#define AKV  8192u
#define KSTG 16384u
#define AKH  0u
#define AVH  8192u
#define ATTN_SMEM (8192 + 2*16384)

__device__ __forceinline__ void attn_load_kv(uint32_t sb, int st, size_t hb, int j0, int tid)
{
    const uint32_t base = sb + AKV + (uint32_t)st * KSTG;
#pragma unroll
    for (int i = 0; i < 4; ++i) {
        int idx = tid + i*128;               // 0..511
        int row = idx >> 3, c16 = idx & 7;
        uint32_t so = SWZ(row*128 + c16*16);
        size_t g = (hb + j0 + row)*HDIM + c16*8;
        cp16(base + AKH + so, g_Kh + g);
        cp16(base + AVH + so, g_Vh + g);
    }
}

__global__ __launch_bounds__(128, 3) void attn_hmma()
{
    extern __shared__ char smem[];
    const uint32_t sb = smem_u32(smem);
    const int tid = threadIdx.x, lane = tid & 31, wid = tid >> 5;
    const int qb = gridDim.x - 1 - blockIdx.x;   // heavy CTAs first
    const int h = blockIdx.y, b = blockIdx.z;
    const int q0 = qb * 64;
    const size_t hb = ((size_t)b*HH + h) * SS;

    // Q tile: 64 x 64 f16 = 8KB
#pragma unroll
    for (int i = 0; i < 4; ++i) {
        int idx = tid + i*128;               // 0..511
        int row = idx >> 3, c16 = idx & 7;
        uint32_t so = SWZ(row*128 + c16*16);
        cp16(sb + AQ + so, g_Qh + (hb + q0 + row)*HDIM + c16*8);
    }
    attn_load_kv(sb, 0, hb, 0, tid);
    CP_COMMIT();

    const uint32_t ones2 = 0x3C003C00u;      // __half2(1,1)
    const uint32_t ones_frag[2] = { ones2, ones2 };

    uint32_t fq[4][4];
    float oacc[8][4];
    float lacc[4];
#pragma unroll
    for (int nt = 0; nt < 8; ++nt)
#pragma unroll
        for (int e = 0; e < 4; ++e) oacc[nt][e] = 0.f;
#pragma unroll
    for (int e = 0; e < 4; ++e) lacc[e] = 0.f;
    float m0 = -1e30f, m1 = -1e30f;

    const int rbase = q0 + 16*wid + (lane >> 2);
    const int ntiles = qb + 1;

    for (int kt = 0; kt < ntiles; ++kt) {
        const int j0 = kt * 64;
        if (kt + 1 < ntiles) {
            attn_load_kv(sb, (kt+1) & 1, hb, j0 + 64, tid);
            CP_COMMIT();
            CP_WAIT1();
        } else {
            CP_WAIT0();
        }
        __syncthreads();

        if (kt == 0) {
#pragma unroll
            for (int t = 0; t < 4; ++t) {
                uint32_t ao = SWZ((16*wid + (lane & 15))*128 + (t*16 + (lane >> 4)*8)*2);
                ldsm4(fq[t], sb + AQ + ao);
            }
        }

        const uint32_t kb = sb + AKV + (uint32_t)(kt & 1) * KSTG;

        // S = Q K^T
        float sacc[8][4];
#pragma unroll
        for (int nt = 0; nt < 8; ++nt)
#pragma unroll
            for (int e = 0; e < 4; ++e) sacc[nt][e] = 0.f;

#pragma unroll
        for (int t = 0; t < 4; ++t) {
#pragma unroll
            for (int p = 0; p < 4; ++p) {
                uint32_t bo_ = SWZ((16*p + (lane & 7) + ((lane & 16) >> 1))*128 + (t*16 + (lane & 8))*2);
                uint32_t kbh[4];
                ldsm4(kbh, kb + AKH + bo_);
                mma16816h(sacc[2*p],   fq[t], &kbh[0]);
                mma16816h(sacc[2*p+1], fq[t], &kbh[2]);
            }
        }

        // causal mask + online softmax (exp2); ballot-gated rescale
        uint32_t pp[8][2];
        if (j0 + 63 > rbase) {
#pragma unroll
            for (int nt = 0; nt < 8; ++nt) {
                int cg = j0 + 8*nt + 2*(lane & 3);
                if (cg   > rbase)     sacc[nt][0] = -1e30f;
                if (cg+1 > rbase)     sacc[nt][1] = -1e30f;
                if (cg   > rbase + 8) sacc[nt][2] = -1e30f;
                if (cg+1 > rbase + 8) sacc[nt][3] = -1e30f;
            }
        }
        float mx0 = -1e30f, mx1 = -1e30f;
#pragma unroll
        for (int nt = 0; nt < 8; ++nt) {
            mx0 = fmaxf(mx0, fmaxf(sacc[nt][0], sacc[nt][1]));
            mx1 = fmaxf(mx1, fmaxf(sacc[nt][2], sacc[nt][3]));
        }
        mx0 = fmaxf(mx0, __shfl_xor_sync(0xffffffffu, mx0, 1));
        mx0 = fmaxf(mx0, __shfl_xor_sync(0xffffffffu, mx0, 2));
        mx1 = fmaxf(mx1, __shfl_xor_sync(0xffffffffu, mx1, 1));
        mx1 = fmaxf(mx1, __shfl_xor_sync(0xffffffffu, mx1, 2));
        const float mn0 = fmaxf(m0, mx0), mn1 = fmaxf(m1, mx1);
        const bool upd = (mn0 > m0) || (mn1 > m1);
        const float c0f = ex2f(m0 - mn0), c1f = ex2f(m1 - mn1);
        m0 = mn0; m1 = mn1;
#pragma unroll
        for (int nt = 0; nt < 8; ++nt) {
            pp[nt][0] = ex2pack(sacc[nt][0] - mn0, sacc[nt][1] - mn0);
            pp[nt][1] = ex2pack(sacc[nt][2] - mn1, sacc[nt][3] - mn1);
        }
        if (__ballot_sync(0xffffffffu, upd)) {
#pragma unroll
            for (int nt = 0; nt < 8; ++nt) {
                oacc[nt][0] *= c0f; oacc[nt][1] *= c0f;
                oacc[nt][2] *= c1f; oacc[nt][3] *= c1f;
            }
            lacc[0] *= c0f; lacc[1] *= c0f;
            lacc[2] *= c1f; lacc[3] *= c1f;
        }

        // O += P V ; l += P @ ones
#pragma unroll
        for (int kc = 0; kc < 4; ++kc) {
            uint32_t pa[4] = { pp[2*kc][0], pp[2*kc][1],
                               pp[2*kc+1][0], pp[2*kc+1][1] };
            mma16816h(lacc, pa, ones_frag);
#pragma unroll
            for (int p = 0; p < 4; ++p) {
                uint32_t vo = SWZ((kc*16 + (lane & 15))*128 + (16*p + ((lane >> 1) & 8))*2);
                uint32_t vbh[4];
                ldsm4t(vbh, kb + AVH + vo);
                mma16816h(oacc[2*p],   pa, &vbh[0]);
                mma16816h(oacc[2*p+1], pa, &vbh[2]);
            }
        }
        __syncthreads();
    }

    // epilogue: normalize, store ctx f16
    const float inv0 = 1.f / lacc[0], inv1 = 1.f / lacc[2];
    const size_t tok = ((size_t)b*SS + rbase)*DD + h*HDIM;
#pragma unroll
    for (int nt = 0; nt < 8; ++nt) {
        int col = 8*nt + 2*(lane & 3);
        *(uint32_t*)(g_Ch + tok + col)        = pk_h2(oacc[nt][0]*inv0, oacc[nt][1]*inv0);
        *(uint32_t*)(g_Ch + tok + 8*DD + col) = pk_h2(oacc[nt][2]*inv1, oacc[nt][3]*inv1);
    }
}

// ---------------- launch ----------------
extern "C" void kernel_launch(void* const* d_in, const int* in_sizes, int n_in,
                              void* d_out, int out_size)
{
    const float* x  = (const float*)d_in[0];
    const float* Wq = (const float*)d_in[1];
    const float* Wk = (const float*)d_in[2];
    const float* Wv = (const float*)d_in[3];
    const float* Wo = (const float*)d_in[4];
    const float* bo = (const float*)d_in[5];
    float* out = (float*)d_out;
    (void)in_sizes; (void)n_in; (void)out_size;

    static bool attr_done = false;
    if (!attr_done) {
        cudaFuncSetAttribute(qkv_hmma, cudaFuncAttributeMaxDynamicSharedMemorySize, GEMM_SMEM);
        cudaFuncSetAttribute(out_hmma, cudaFuncAttributeMaxDynamicSharedMemorySize, GEMM_SMEM);
        cudaFuncSetAttribute(attn_hmma, cudaFuncAttributeMaxDynamicSharedMemorySize, ATTN_SMEM);
        attr_done = true;
    }

    split_all<<<(XN4 + 4*WN4) / 256, 256>>>(x, Wq, Wk, Wv, Wo);

    dim3 qkv_grid(DD/128, MTOT/128, 3);
    qkv_hmma<<<qkv_grid, 128, GEMM_SMEM>>>();

    dim3 attn_grid(SS/64, HH, BB);
    attn_hmma<<<attn_grid, 128, ATTN_SMEM>>>();

    dim3 out_grid(DD/128, MTOT/128, 1);
    out_hmma<<<out_grid, 128, GEMM_SMEM>>>(out, bo);
}